// round 2
// baseline (speedup 1.0000x reference)
#include <cuda_runtime.h>
#include <cuda_bf16.h>
#include <cstdint>

#define Bb 4
#define Tt 1024
#define Ss 128
#define Cc 1024
#define Hh 16
#define NLAYER 8
#define VOC 4096
#define Lseq 2048
#define DH 64

#define N_BLC (Bb*Lseq*Cc)
#define N_MID (Bb*Lseq*2*Cc)
#define N_HF  (Bb*Tt*Cc)
__device__ float g_scratch[6*N_BLC + N_MID + N_HF];

__device__ __forceinline__ void ldsm4(uint32_t r[4], const __nv_bfloat16* p) {
    uint32_t a = (uint32_t)__cvta_generic_to_shared(p);
    asm volatile("ldmatrix.sync.aligned.m8n8.x4.shared.b16 {%0,%1,%2,%3}, [%4];"
        : "=r"(r[0]), "=r"(r[1]), "=r"(r[2]), "=r"(r[3]) : "r"(a));
}
__device__ __forceinline__ void mma_bf16(float c[4], const uint32_t a[4], const uint32_t b[2]) {
    asm volatile("mma.sync.aligned.m16n8k16.row.col.f32.bf16.bf16.f32 "
        "{%0,%1,%2,%3}, {%4,%5,%6,%7}, {%8,%9}, {%0,%1,%2,%3};"
        : "+f"(c[0]), "+f"(c[1]), "+f"(c[2]), "+f"(c[3])
        : "r"(a[0]), "r"(a[1]), "r"(a[2]), "r"(a[3]), "r"(b[0]), "r"(b[1]));
}

// out[M,N] = act(A[M,K] @ W[K,N] + bias) (+ res). fp32 I/O, split-bf16 MMA.
// BM=BN=128, BK=32, 256 thr = 8 warps (4x2), warp tile 32x64.
template<int ACT, bool HASBIAS, bool HASRES>
__global__ __launch_bounds__(256) void gemm_kernel(
    const float* __restrict__ A, const float* __restrict__ W,
    const float* __restrict__ bias, const float* __restrict__ res,
    float* __restrict__ out, int M, int N, int K)
{
    const int LDK = 40;
    __shared__ __nv_bfloat16 AshH[128*LDK], AshL[128*LDK];
    __shared__ __nv_bfloat16 BshH[128*LDK], BshL[128*LDK];

    int tid = threadIdx.x, lane = tid & 31, warp = tid >> 5;
    int bm = blockIdx.y * 128, bn = blockIdx.x * 128;
    int wm = (warp >> 1) * 32, wn = (warp & 1) * 64;

    float acc[2][8][4];
    #pragma unroll
    for (int i = 0; i < 2; i++)
        #pragma unroll
        for (int j = 0; j < 8; j++)
            #pragma unroll
            for (int q = 0; q < 4; q++) acc[i][j][q] = 0.f;

    int ar = tid >> 1, ac = (tid & 1) * 16;
    const float* Ap = A + (size_t)(bm + ar) * K + ac;
    int wk = tid >> 3, wn2 = (tid & 7) * 16;
    const float* Wp = W + (size_t)wk * N + bn + wn2;

    for (int k0 = 0; k0 < K; k0 += 32) {
        #pragma unroll
        for (int j = 0; j < 4; j++) {
            float4 v = *(const float4*)(Ap + k0 + j*4);
            int off = ar*LDK + ac + j*4;
            float f[4] = {v.x, v.y, v.z, v.w};
            #pragma unroll
            for (int e = 0; e < 4; e++) {
                __nv_bfloat16 hh = __float2bfloat16_rn(f[e]);
                AshH[off+e] = hh;
                AshL[off+e] = __float2bfloat16_rn(f[e] - __bfloat162float(hh));
            }
        }
        #pragma unroll
        for (int j = 0; j < 4; j++) {
            float4 v = *(const float4*)(Wp + (size_t)k0 * N + j*4);
            float f[4] = {v.x, v.y, v.z, v.w};
            #pragma unroll
            for (int e = 0; e < 4; e++) {
                int nn = wn2 + j*4 + e;
                __nv_bfloat16 hh = __float2bfloat16_rn(f[e]);
                BshH[nn*LDK + wk] = hh;
                BshL[nn*LDK + wk] = __float2bfloat16_rn(f[e] - __bfloat162float(hh));
            }
        }
        __syncthreads();

        #pragma unroll
        for (int ks = 0; ks < 2; ks++) {
            uint32_t aH[2][4], aL[2][4];
            #pragma unroll
            for (int mi = 0; mi < 2; mi++) {
                int row = wm + mi*16 + (lane & 15);
                int col = ks*16 + ((lane >> 4) << 3);
                ldsm4(aH[mi], &AshH[row*LDK + col]);
                ldsm4(aL[mi], &AshL[row*LDK + col]);
            }
            uint32_t bH[8][2], bL[8][2];
            #pragma unroll
            for (int pi = 0; pi < 4; pi++) {
                int nr = wn + pi*16 + ((lane >> 4) << 3) + (lane & 7);
                int kc = ks*16 + (((lane >> 3) & 1) << 3);
                uint32_t t[4];
                ldsm4(t, &BshH[nr*LDK + kc]);
                bH[2*pi][0] = t[0]; bH[2*pi][1] = t[1];
                bH[2*pi+1][0] = t[2]; bH[2*pi+1][1] = t[3];
                ldsm4(t, &BshL[nr*LDK + kc]);
                bL[2*pi][0] = t[0]; bL[2*pi][1] = t[1];
                bL[2*pi+1][0] = t[2]; bL[2*pi+1][1] = t[3];
            }
            #pragma unroll
            for (int mi = 0; mi < 2; mi++)
                #pragma unroll
                for (int nj = 0; nj < 8; nj++) {
                    mma_bf16(acc[mi][nj], aH[mi], bH[nj]);
                    mma_bf16(acc[mi][nj], aH[mi], bL[nj]);
                    mma_bf16(acc[mi][nj], aL[mi], bH[nj]);
                }
        }
        __syncthreads();
    }

    int g = lane >> 2, tg = lane & 3;
    #pragma unroll
    for (int mi = 0; mi < 2; mi++)
        #pragma unroll
        for (int nj = 0; nj < 8; nj++) {
            int r0 = bm + wm + mi*16 + g;
            int c0 = bn + wn + nj*8 + tg*2;
            #pragma unroll
            for (int q = 0; q < 4; q++) {
                int r = r0 + (q >> 1) * 8;
                int c = c0 + (q & 1);
                float v = acc[mi][nj][q];
                if (HASBIAS) v += bias[c];
                if (ACT == 1) v = tanhf(v);
                else if (ACT == 2) v = 0.5f * v * (1.0f + erff(v * 0.70710678f));
                if (HASRES) v += res[(size_t)r * N + c];
                out[(size_t)r * N + c] = v;
            }
        }
}

// LayerNorm over C=1024, block per row. gather: read row b*L+2t+1 for out-row b*T+t.
__global__ __launch_bounds__(256) void ln_kernel(
    const float* __restrict__ x, const float* __restrict__ g,
    const float* __restrict__ b, float* __restrict__ out, int gather)
{
    int row = blockIdx.x;
    int src = gather ? ((row / Tt) * Lseq + 2 * (row % Tt) + 1) : row;
    float4 v = ((const float4*)(x + (size_t)src * Cc))[threadIdx.x];
    float s = v.x + v.y + v.z + v.w;
    float q = v.x*v.x + v.y*v.y + v.z*v.z + v.w*v.w;
    #pragma unroll
    for (int o = 16; o; o >>= 1) {
        s += __shfl_xor_sync(0xffffffffu, s, o);
        q += __shfl_xor_sync(0xffffffffu, q, o);
    }
    __shared__ float ss[8], sq[8];
    int w = threadIdx.x >> 5;
    if ((threadIdx.x & 31) == 0) { ss[w] = s; sq[w] = q; }
    __syncthreads();
    s = 0.f; q = 0.f;
    #pragma unroll
    for (int i = 0; i < 8; i++) { s += ss[i]; q += sq[i]; }
    float mean = s * (1.0f / Cc);
    float rstd = rsqrtf(q * (1.0f / Cc) - mean * mean + 1e-5f);
    float4 gv = ((const float4*)g)[threadIdx.x];
    float4 bv = ((const float4*)b)[threadIdx.x];
    float4 o4;
    o4.x = (v.x - mean) * rstd * gv.x + bv.x;
    o4.y = (v.y - mean) * rstd * gv.y + bv.y;
    o4.z = (v.z - mean) * rstd * gv.z + bv.z;
    o4.w = (v.w - mean) * rstd * gv.w + bv.w;
    ((float4*)(out + (size_t)row * Cc))[threadIdx.x] = o4;
}

// token assembly: even=state emb, odd=tanh(action emb), + gpe + pos
__global__ __launch_bounds__(256) void assemble_kernel(
    const float* __restrict__ SE, const int* __restrict__ actions,
    const int* __restrict__ tsteps, const float* __restrict__ act_table,
    const float* __restrict__ pos_emb, const float* __restrict__ gpe_table,
    float* __restrict__ x)
{
    int bt = blockIdx.x;
    int b = bt / Tt, t = bt % Tt;
    int a = actions[bt];
    int ts = tsteps[bt];
    size_t row0 = (size_t)(b * Lseq + 2*t) * Cc;
    for (int c = threadIdx.x; c < Cc; c += 256) {
        float gp = gpe_table[(size_t)ts * Cc + c];
        x[row0 + c]      = SE[(size_t)bt * Cc + c] + gp + pos_emb[(size_t)(2*t) * Cc + c];
        x[row0 + Cc + c] = tanhf(act_table[(size_t)a * Cc + c]) + gp + pos_emb[(size_t)(2*t+1) * Cc + c];
    }
}

// causal flash attention, fp32. grid(L/64, B*H), 256 thr. 4 thr per q-row.
__global__ __launch_bounds__(256) void attn_kernel(
    const float* __restrict__ Q, const float* __restrict__ Kp,
    const float* __restrict__ Vp, float* __restrict__ O)
{
    __shared__ float Qsh[64][65];
    __shared__ float Ksh[32][65];
    __shared__ float Vsh[32][65];
    __shared__ float Ssh[64][36];

    int tid = threadIdx.x;
    int b = blockIdx.y >> 4, h = blockIdx.y & 15;
    int q0 = blockIdx.x * 64;

    for (int i = tid; i < 64*64; i += 256) {
        int r = i >> 6, d = i & 63;
        Qsh[r][d] = Q[(size_t)(b*Lseq + q0 + r)*Cc + h*DH + d];
    }

    int qr = tid >> 2, dq = tid & 3;
    float m = -1e30f, l = 0.f;
    float acc[16];
    #pragma unroll
    for (int i = 0; i < 16; i++) acc[i] = 0.f;

    for (int j0 = 0; j0 < q0 + 64; j0 += 32) {
        __syncthreads();
        for (int i = tid; i < 32*64; i += 256) {
            int r = i >> 6, d = i & 63;
            size_t src = (size_t)(b*Lseq + j0 + r)*Cc + h*DH + d;
            Ksh[r][d] = Kp[src];
            Vsh[r][d] = Vp[src];
        }
        __syncthreads();

        float tmax = -1e30f, sreg[8];
        #pragma unroll
        for (int jj = 0; jj < 8; jj++) {
            int j = dq*8 + jj;
            float s = 0.f;
            #pragma unroll
            for (int d = 0; d < 64; d++) s += Qsh[qr][d] * Ksh[j][d];
            s *= 0.125f;
            if (j0 + j > q0 + qr) s = -1e30f;
            sreg[jj] = s;
            tmax = fmaxf(tmax, s);
        }
        tmax = fmaxf(tmax, __shfl_xor_sync(0xffffffffu, tmax, 1));
        tmax = fmaxf(tmax, __shfl_xor_sync(0xffffffffu, tmax, 2));
        float mnew = fmaxf(m, tmax);
        float alpha = expf(m - mnew);
        float psum = 0.f;
        #pragma unroll
        for (int jj = 0; jj < 8; jj++) {
            float p = expf(sreg[jj] - mnew);
            Ssh[qr][dq*8 + jj] = p;
            psum += p;
        }
        psum += __shfl_xor_sync(0xffffffffu, psum, 1);
        psum += __shfl_xor_sync(0xffffffffu, psum, 2);
        l = l * alpha + psum;
        m = mnew;
        __syncwarp();

        #pragma unroll
        for (int d = 0; d < 16; d++) acc[d] *= alpha;
        for (int j = 0; j < 32; j++) {
            float p = Ssh[qr][j];
            #pragma unroll
            for (int d = 0; d < 16; d++) acc[d] += p * Vsh[j][dq*16 + d];
        }
    }
    float rl = 1.f / l;
    size_t row = (size_t)(b*Lseq + q0 + qr);
    #pragma unroll
    for (int d = 0; d < 16; d++)
        O[row*Cc + h*DH + dq*16 + d] = acc[d] * rl;
}

extern "C" void kernel_launch(void* const* d_in, const int* in_sizes, int n_in,
                              void* d_out, int out_size) {
    const float* states   = (const float*)d_in[0];
    const int*   actions  = (const int*)d_in[1];
    const int*   tsteps   = (const int*)d_in[2];
    const float* W_se     = (const float*)d_in[3];
    const float* b_se     = (const float*)d_in[4];
    const float* act_tab  = (const float*)d_in[5];
    const float* pos_emb  = (const float*)d_in[6];
    const float* gpe      = (const float*)d_in[7];
    const float* ln1_g    = (const float*)d_in[8];
    const float* ln1_b    = (const float*)d_in[9];
    const float* Wq       = (const float*)d_in[10];
    const float* bq       = (const float*)d_in[11];
    const float* Wk       = (const float*)d_in[12];
    const float* bk       = (const float*)d_in[13];
    const float* Wv       = (const float*)d_in[14];
    const float* bv       = (const float*)d_in[15];
    const float* Wo       = (const float*)d_in[16];
    const float* bo       = (const float*)d_in[17];
    const float* ln2_g    = (const float*)d_in[18];
    const float* ln2_b    = (const float*)d_in[19];
    const float* W1       = (const float*)d_in[20];
    const float* b1       = (const float*)d_in[21];
    const float* W2       = (const float*)d_in[22];
    const float* b2       = (const float*)d_in[23];
    const float* lnf_g    = (const float*)d_in[24];
    const float* lnf_b    = (const float*)d_in[25];
    const float* W_head   = (const float*)d_in[26];
    float* out = (float*)d_out;

    float* base = nullptr;
    cudaGetSymbolAddress((void**)&base, g_scratch);
    float* X   = base;
    float* X2  = X  + N_BLC;
    float* Hb  = X2 + N_BLC;
    float* Qb  = Hb + N_BLC;
    float* Kb  = Qb + N_BLC;
    float* Vb  = Kb + N_BLC;
    float* MID = Vb + N_BLC;
    float* HF  = MID + N_MID;

    const int Mx = Bb * Lseq;          // 8192
    const int Mh = Bb * Tt;            // 4096
    dim3 thr(256);

    // state encoder: tanh(states @ W_se + b_se)
    gemm_kernel<1,true,false><<<dim3(Cc/128, Mh/128), thr>>>(states, W_se, b_se, nullptr, HF, Mh, Cc, Ss);
    assemble_kernel<<<Mh, thr>>>(HF, actions, tsteps, act_tab, pos_emb, gpe, X);

    for (int l = 0; l < NLAYER; l++) {
        const float* wq = Wq + (size_t)l*Cc*Cc;
        const float* wk = Wk + (size_t)l*Cc*Cc;
        const float* wv = Wv + (size_t)l*Cc*Cc;
        const float* wo = Wo + (size_t)l*Cc*Cc;
        const float* w1 = W1 + (size_t)l*Cc*2*Cc;
        const float* w2 = W2 + (size_t)l*2*Cc*Cc;

        ln_kernel<<<Mx, thr>>>(X, ln1_g + l*Cc, ln1_b + l*Cc, Hb, 0);
        gemm_kernel<0,true,false><<<dim3(Cc/128, Mx/128), thr>>>(Hb, wq, bq + l*Cc, nullptr, Qb, Mx, Cc, Cc);
        gemm_kernel<0,true,false><<<dim3(Cc/128, Mx/128), thr>>>(Hb, wk, bk + l*Cc, nullptr, Kb, Mx, Cc, Cc);
        gemm_kernel<0,true,false><<<dim3(Cc/128, Mx/128), thr>>>(Hb, wv, bv + l*Cc, nullptr, Vb, Mx, Cc, Cc);
        attn_kernel<<<dim3(Lseq/64, Bb*Hh), thr>>>(Qb, Kb, Vb, Hb);
        gemm_kernel<0,true,true><<<dim3(Cc/128, Mx/128), thr>>>(Hb, wo, bo + l*Cc, X, X2, Mx, Cc, Cc);
        ln_kernel<<<Mx, thr>>>(X2, ln2_g + l*Cc, ln2_b + l*Cc, Hb, 0);
        gemm_kernel<2,true,false><<<dim3(2*Cc/128, Mx/128), thr>>>(Hb, w1, b1 + l*2*Cc, nullptr, MID, Mx, 2*Cc, Cc);
        gemm_kernel<0,true,true><<<dim3(Cc/128, Mx/128), thr>>>(MID, w2, b2 + l*Cc, X2, X, Mx, Cc, 2*Cc);
    }

    ln_kernel<<<Mh, thr>>>(X, lnf_g, lnf_b, HF, 1);
    gemm_kernel<0,false,false><<<dim3(VOC/128, Mh/128), thr>>>(HF, W_head, nullptr, nullptr, out, Mh, VOC, Cc);
}

// round 3
// speedup vs baseline: 2.4804x; 2.4804x over previous
#include <cuda_runtime.h>
#include <cuda_bf16.h>
#include <cstdint>

#define Bb 4
#define Tt 1024
#define Ss 128
#define Cc 1024
#define NLAYER 8
#define VOC 4096
#define Lseq 2048

#define N_BLC (Bb*Lseq*Cc)
#define N_HF  (Bb*Tt*Cc)

__device__ float g_f32[5*N_BLC + N_HF];                 // X,X2,Qb,Kb,Vb,HF
__device__ __nv_bfloat16 g_bf[219414528];               // all bf16 hi/lo planes

// ---------------- helpers ----------------
__device__ __forceinline__ void ldsm4(uint32_t r[4], const __nv_bfloat16* p) {
    uint32_t a = (uint32_t)__cvta_generic_to_shared(p);
    asm volatile("ldmatrix.sync.aligned.m8n8.x4.shared.b16 {%0,%1,%2,%3}, [%4];"
        : "=r"(r[0]), "=r"(r[1]), "=r"(r[2]), "=r"(r[3]) : "r"(a));
}
__device__ __forceinline__ void mma_bf16(float c[4], const uint32_t a[4], const uint32_t b[2]) {
    asm volatile("mma.sync.aligned.m16n8k16.row.col.f32.bf16.bf16.f32 "
        "{%0,%1,%2,%3}, {%4,%5,%6,%7}, {%8,%9}, {%0,%1,%2,%3};"
        : "+f"(c[0]), "+f"(c[1]), "+f"(c[2]), "+f"(c[3])
        : "r"(a[0]), "r"(a[1]), "r"(a[2]), "r"(a[3]), "r"(b[0]), "r"(b[1]));
}
__device__ __forceinline__ void cpa16(__nv_bfloat16* dst, const __nv_bfloat16* src) {
    uint32_t d = (uint32_t)__cvta_generic_to_shared(dst);
    asm volatile("cp.async.cg.shared.global [%0], [%1], 16;" :: "r"(d), "l"(src));
}
__device__ __forceinline__ void split1(float v, __nv_bfloat16& h, __nv_bfloat16& l) {
    h = __float2bfloat16_rn(v);
    l = __float2bfloat16_rn(v - __bfloat162float(h));
}

// ---------------- GEMM: out = act(A@W + bias)(+res); A,W as bf16 hi/lo planes ----------------
// A planes [M,K] row-major; W planes PRE-TRANSPOSED [N,K] row-major.
// BM=BN=128, BK=32, 256 thr, 2-stage cp.async pipeline. 3-term split MMA.
template<int ACT, bool HASBIAS, bool HASRES, bool PLANES>
__global__ __launch_bounds__(256) void gemm_kernel(
    const __nv_bfloat16* __restrict__ Ah, const __nv_bfloat16* __restrict__ Al,
    const __nv_bfloat16* __restrict__ Wh, const __nv_bfloat16* __restrict__ Wl,
    const float* __restrict__ bias, const float* __restrict__ res,
    float* __restrict__ out, __nv_bfloat16* __restrict__ outH, __nv_bfloat16* __restrict__ outL,
    int M, int N, int K)
{
    extern __shared__ __nv_bfloat16 sm[];
    const int TILE = 128*40;
    int tid = threadIdx.x, lane = tid & 31, warp = tid >> 5;
    int bm = blockIdx.y * 128, bn = blockIdx.x * 128;
    int wm = (warp >> 1) * 32, wn = (warp & 1) * 64;

    float acc[2][8][4];
    #pragma unroll
    for (int i = 0; i < 2; i++)
        #pragma unroll
        for (int j = 0; j < 8; j++)
            #pragma unroll
            for (int q = 0; q < 4; q++) acc[i][j][q] = 0.f;

    int niter = K >> 5;

    // stage loader: 2048 16B-chunks (4 tiles x 128 rows x 4 chunks), 8 per thread
    #define ISSUE(ST, K0) do {                                                  \
        int _k0 = (K0);                                                         \
        _Pragma("unroll")                                                       \
        for (int _i = 0; _i < 8; _i++) {                                        \
            int _id = tid + (_i << 8);                                          \
            int _tile = _id >> 9;                                               \
            int _r = (_id >> 2) & 127;                                          \
            int _c = (_id & 3) << 3;                                            \
            const __nv_bfloat16* _src =                                         \
                (_tile == 0) ? Ah + (size_t)(bm + _r) * K + _k0 + _c :          \
                (_tile == 1) ? Al + (size_t)(bm + _r) * K + _k0 + _c :          \
                (_tile == 2) ? Wh + (size_t)(bn + _r) * K + _k0 + _c :          \
                               Wl + (size_t)(bn + _r) * K + _k0 + _c;           \
            cpa16(sm + ((ST)*4 + _tile)*TILE + _r*40 + _c, _src);               \
        }                                                                       \
        asm volatile("cp.async.commit_group;" ::: "memory");                    \
    } while (0)

    ISSUE(0, 0);
    for (int it = 0; it < niter; ++it) {
        if (it + 1 < niter) {
            ISSUE((it + 1) & 1, (it + 1) << 5);
            asm volatile("cp.async.wait_group 1;" ::: "memory");
        } else {
            asm volatile("cp.async.wait_group 0;" ::: "memory");
        }
        __syncthreads();
        const __nv_bfloat16* AshH = sm + (((it&1)*4 + 0) * TILE);
        const __nv_bfloat16* AshL = sm + (((it&1)*4 + 1) * TILE);
        const __nv_bfloat16* BshH = sm + (((it&1)*4 + 2) * TILE);
        const __nv_bfloat16* BshL = sm + (((it&1)*4 + 3) * TILE);

        #pragma unroll
        for (int ks = 0; ks < 2; ks++) {
            uint32_t aH[2][4], aL[2][4];
            #pragma unroll
            for (int mi = 0; mi < 2; mi++) {
                int row = wm + mi*16 + (lane & 15);
                int col = ks*16 + ((lane >> 4) << 3);
                ldsm4(aH[mi], &AshH[row*40 + col]);
                ldsm4(aL[mi], &AshL[row*40 + col]);
            }
            uint32_t bH[8][2], bL[8][2];
            #pragma unroll
            for (int pi = 0; pi < 4; pi++) {
                int nr = wn + pi*16 + ((lane >> 4) << 3) + (lane & 7);
                int kc = ks*16 + (((lane >> 3) & 1) << 3);
                uint32_t t[4];
                ldsm4(t, &BshH[nr*40 + kc]);
                bH[2*pi][0] = t[0]; bH[2*pi][1] = t[1];
                bH[2*pi+1][0] = t[2]; bH[2*pi+1][1] = t[3];
                ldsm4(t, &BshL[nr*40 + kc]);
                bL[2*pi][0] = t[0]; bL[2*pi][1] = t[1];
                bL[2*pi+1][0] = t[2]; bL[2*pi+1][1] = t[3];
            }
            #pragma unroll
            for (int mi = 0; mi < 2; mi++)
                #pragma unroll
                for (int nj = 0; nj < 8; nj++) {
                    mma_bf16(acc[mi][nj], aH[mi], bH[nj]);
                    mma_bf16(acc[mi][nj], aH[mi], bL[nj]);
                    mma_bf16(acc[mi][nj], aL[mi], bH[nj]);
                }
        }
        __syncthreads();
    }
    #undef ISSUE

    int g = lane >> 2, tg = lane & 3;
    #pragma unroll
    for (int mi = 0; mi < 2; mi++)
        #pragma unroll
        for (int nj = 0; nj < 8; nj++) {
            int r0 = bm + wm + mi*16 + g;
            int c0 = bn + wn + nj*8 + tg*2;
            float v[4];
            #pragma unroll
            for (int q = 0; q < 4; q++) {
                float x = acc[mi][nj][q];
                if (HASBIAS) x += bias[c0 + (q & 1)];
                if (ACT == 1) x = tanhf(x);
                else if (ACT == 2) x = 0.5f * x * (1.0f + erff(x * 0.70710678f));
                v[q] = x;
            }
            if (PLANES) {
                #pragma unroll
                for (int half = 0; half < 2; half++) {
                    int r = r0 + half*8;
                    __nv_bfloat16 h0, h1, l0, l1;
                    split1(v[2*half], h0, l0);
                    split1(v[2*half+1], h1, l1);
                    __nv_bfloat162 hh; hh.x = h0; hh.y = h1;
                    __nv_bfloat162 ll; ll.x = l0; ll.y = l1;
                    *(__nv_bfloat162*)&outH[(size_t)r*N + c0] = hh;
                    *(__nv_bfloat162*)&outL[(size_t)r*N + c0] = ll;
                }
            } else {
                #pragma unroll
                for (int q = 0; q < 4; q++) {
                    int r = r0 + (q >> 1) * 8, c = c0 + (q & 1);
                    float x = v[q];
                    if (HASRES) x += res[(size_t)r * N + c];
                    out[(size_t)r * N + c] = x;
                }
            }
        }
}

// ---------------- LayerNorm -> bf16 hi/lo planes ----------------
__global__ __launch_bounds__(256) void ln_kernel(
    const float* __restrict__ x, const float* __restrict__ g,
    const float* __restrict__ b, __nv_bfloat16* __restrict__ oh,
    __nv_bfloat16* __restrict__ ol, int gather)
{
    int row = blockIdx.x;
    int src = gather ? ((row / Tt) * Lseq + 2 * (row % Tt) + 1) : row;
    float4 v = ((const float4*)(x + (size_t)src * Cc))[threadIdx.x];
    float s = v.x + v.y + v.z + v.w;
    float q = v.x*v.x + v.y*v.y + v.z*v.z + v.w*v.w;
    #pragma unroll
    for (int o = 16; o; o >>= 1) {
        s += __shfl_xor_sync(0xffffffffu, s, o);
        q += __shfl_xor_sync(0xffffffffu, q, o);
    }
    __shared__ float ss[8], sq[8];
    int w = threadIdx.x >> 5;
    if ((threadIdx.x & 31) == 0) { ss[w] = s; sq[w] = q; }
    __syncthreads();
    s = 0.f; q = 0.f;
    #pragma unroll
    for (int i = 0; i < 8; i++) { s += ss[i]; q += sq[i]; }
    float mean = s * (1.0f / Cc);
    float rstd = rsqrtf(q * (1.0f / Cc) - mean * mean + 1e-5f);
    float4 gv = ((const float4*)g)[threadIdx.x];
    float4 bv = ((const float4*)b)[threadIdx.x];
    float o4[4];
    o4[0] = (v.x - mean) * rstd * gv.x + bv.x;
    o4[1] = (v.y - mean) * rstd * gv.y + bv.y;
    o4[2] = (v.z - mean) * rstd * gv.z + bv.z;
    o4[3] = (v.w - mean) * rstd * gv.w + bv.w;
    size_t base = (size_t)row * Cc + threadIdx.x * 4;
    __nv_bfloat16 h[4], l[4];
    #pragma unroll
    for (int e = 0; e < 4; e++) split1(o4[e], h[e], l[e]);
    __nv_bfloat162 p;
    p.x=h[0]; p.y=h[1]; *(__nv_bfloat162*)&oh[base]   = p;
    p.x=h[2]; p.y=h[3]; *(__nv_bfloat162*)&oh[base+2] = p;
    p.x=l[0]; p.y=l[1]; *(__nv_bfloat162*)&ol[base]   = p;
    p.x=l[2]; p.y=l[3]; *(__nv_bfloat162*)&ol[base+2] = p;
}

// ---------------- token assembly (fp32 residual stream) ----------------
__global__ __launch_bounds__(256) void assemble_kernel(
    const float* __restrict__ SE, const int* __restrict__ actions,
    const int* __restrict__ tsteps, const float* __restrict__ act_table,
    const float* __restrict__ pos_emb, const float* __restrict__ gpe_table,
    float* __restrict__ x)
{
    int bt = blockIdx.x;
    int b = bt / Tt, t = bt % Tt;
    int a = actions[bt];
    int ts = tsteps[bt];
    size_t row0 = (size_t)(b * Lseq + 2*t) * Cc;
    for (int c = threadIdx.x; c < Cc; c += 256) {
        float gp = gpe_table[(size_t)ts * Cc + c];
        x[row0 + c]      = SE[(size_t)bt * Cc + c] + gp + pos_emb[(size_t)(2*t) * Cc + c];
        x[row0 + Cc + c] = tanhf(act_table[(size_t)a * Cc + c]) + gp + pos_emb[(size_t)(2*t+1) * Cc + c];
    }
}

// ---------------- register-tiled fp32 flash attention ----------------
// grid(L/64, B*H), 256 thr. Thread (tq4=tid>>4, tk=tid&15): 4 q-rows x 4 keys / 4 d-cols.
__global__ __launch_bounds__(256) void attn_kernel(
    const float* __restrict__ Q, const float* __restrict__ Kp,
    const float* __restrict__ Vp, __nv_bfloat16* __restrict__ OH,
    __nv_bfloat16* __restrict__ OL)
{
    extern __shared__ float smf[];
    float (*Qt)[68] = (float(*)[68])smf;            // [d][q], pre-scaled
    float (*Kt)[68] = (float(*)[68])(smf + 64*68);  // [d][k]
    float (*Vs)[68] = (float(*)[68])(smf + 2*64*68);// [k][d]
    float (*Pt)[68] = (float(*)[68])(smf + 3*64*68);// [k][q]

    int tid = threadIdx.x;
    int b = blockIdx.y >> 4, h = blockIdx.y & 15;
    int q0g = blockIdx.x * 64;
    int tq4 = tid >> 4, tk = tid & 15;
    int qb = tq4 << 2, kb = tk << 2;

    for (int i = tid; i < 1024; i += 256) {
        int r = i >> 4, d4 = (i & 15) << 2;
        float4 qv = *(const float4*)&Q[(size_t)(b*Lseq + q0g + r)*Cc + h*64 + d4];
        Qt[d4+0][r] = qv.x * 0.125f; Qt[d4+1][r] = qv.y * 0.125f;
        Qt[d4+2][r] = qv.z * 0.125f; Qt[d4+3][r] = qv.w * 0.125f;
    }

    float m[4] = {-1e30f, -1e30f, -1e30f, -1e30f};
    float l[4] = {0.f, 0.f, 0.f, 0.f};
    float O[4][4];
    #pragma unroll
    for (int i = 0; i < 4; i++)
        #pragma unroll
        for (int j = 0; j < 4; j++) O[i][j] = 0.f;

    for (int j0 = 0; j0 <= q0g; j0 += 64) {
        __syncthreads();
        for (int i = tid; i < 1024; i += 256) {
            int r = i >> 4, d4 = (i & 15) << 2;
            size_t gsrc = (size_t)(b*Lseq + j0 + r)*Cc + h*64 + d4;
            float4 kv = *(const float4*)&Kp[gsrc];
            Kt[d4+0][r] = kv.x; Kt[d4+1][r] = kv.y; Kt[d4+2][r] = kv.z; Kt[d4+3][r] = kv.w;
            *(float4*)&Vs[r][d4] = *(const float4*)&Vp[gsrc];
        }
        __syncthreads();

        float S[4][4];
        #pragma unroll
        for (int i = 0; i < 4; i++)
            #pragma unroll
            for (int j = 0; j < 4; j++) S[i][j] = 0.f;

        #pragma unroll 16
        for (int d = 0; d < 64; d++) {
            float4 qv = *(const float4*)&Qt[d][qb];
            float4 kv = *(const float4*)&Kt[d][kb];
            float qa[4] = {qv.x, qv.y, qv.z, qv.w};
            float ka[4] = {kv.x, kv.y, kv.z, kv.w};
            #pragma unroll
            for (int i = 0; i < 4; i++)
                #pragma unroll
                for (int j = 0; j < 4; j++) S[i][j] += qa[i] * ka[j];
        }

        #pragma unroll
        for (int i = 0; i < 4; i++) {
            int qq = q0g + qb + i;
            #pragma unroll
            for (int j = 0; j < 4; j++)
                if (j0 + kb + j > qq) S[i][j] = -1e30f;
            float rmax = fmaxf(fmaxf(S[i][0], S[i][1]), fmaxf(S[i][2], S[i][3]));
            rmax = fmaxf(rmax, __shfl_xor_sync(0xffffffffu, rmax, 1));
            rmax = fmaxf(rmax, __shfl_xor_sync(0xffffffffu, rmax, 2));
            rmax = fmaxf(rmax, __shfl_xor_sync(0xffffffffu, rmax, 4));
            rmax = fmaxf(rmax, __shfl_xor_sync(0xffffffffu, rmax, 8));
            float mnew = fmaxf(m[i], rmax);
            float alpha = expf(m[i] - mnew);
            float rsum = 0.f;
            #pragma unroll
            for (int j = 0; j < 4; j++) {
                float p = expf(S[i][j] - mnew);
                Pt[kb + j][qb + i] = p;
                rsum += p;
            }
            rsum += __shfl_xor_sync(0xffffffffu, rsum, 1);
            rsum += __shfl_xor_sync(0xffffffffu, rsum, 2);
            rsum += __shfl_xor_sync(0xffffffffu, rsum, 4);
            rsum += __shfl_xor_sync(0xffffffffu, rsum, 8);
            l[i] = l[i] * alpha + rsum;
            m[i] = mnew;
            #pragma unroll
            for (int dd = 0; dd < 4; dd++) O[i][dd] *= alpha;
        }
        __syncthreads();

        #pragma unroll 8
        for (int kk = 0; kk < 64; kk++) {
            float4 pv = *(const float4*)&Pt[kk][qb];
            float4 vv = *(const float4*)&Vs[kk][kb];
            float pa[4] = {pv.x, pv.y, pv.z, pv.w};
            float va[4] = {vv.x, vv.y, vv.z, vv.w};
            #pragma unroll
            for (int i = 0; i < 4; i++)
                #pragma unroll
                for (int dd = 0; dd < 4; dd++) O[i][dd] += pa[i] * va[dd];
        }
    }

    #pragma unroll
    for (int i = 0; i < 4; i++) {
        float rl = 1.f / l[i];
        size_t base = (size_t)(b*Lseq + q0g + qb + i)*Cc + h*64 + kb;
        __nv_bfloat16 hh[4], ll[4];
        #pragma unroll
        for (int dd = 0; dd < 4; dd++) split1(O[i][dd] * rl, hh[dd], ll[dd]);
        __nv_bfloat162 p;
        p.x=hh[0]; p.y=hh[1]; *(__nv_bfloat162*)&OH[base]   = p;
        p.x=hh[2]; p.y=hh[3]; *(__nv_bfloat162*)&OH[base+2] = p;
        p.x=ll[0]; p.y=ll[1]; *(__nv_bfloat162*)&OL[base]   = p;
        p.x=ll[2]; p.y=ll[3]; *(__nv_bfloat162*)&OL[base+2] = p;
    }
}

// ---------------- weight transpose+split: W[K,N] fp32 -> Wt hi/lo [N,K] bf16 ----------------
__global__ __launch_bounds__(256) void wsplit_kernel(
    const float* __restrict__ W, __nv_bfloat16* __restrict__ Wh,
    __nv_bfloat16* __restrict__ Wl, int K, int N)
{
    __shared__ float tile[32][33];
    int k0 = blockIdx.y * 32, n0 = blockIdx.x * 32;
    int tx = threadIdx.x & 31, ty = threadIdx.x >> 5;
    #pragma unroll
    for (int r = ty; r < 32; r += 8)
        tile[r][tx] = W[(size_t)(k0 + r) * N + n0 + tx];
    __syncthreads();
    #pragma unroll
    for (int r = ty; r < 32; r += 8) {
        float v = tile[tx][r];
        __nv_bfloat16 h, l;
        split1(v, h, l);
        size_t dst = (size_t)(n0 + r) * K + k0 + tx;
        Wh[dst] = h; Wl[dst] = l;
    }
}

// ---------------- elementwise split (states) ----------------
__global__ __launch_bounds__(256) void esplit_kernel(
    const float* __restrict__ x, __nv_bfloat16* __restrict__ h,
    __nv_bfloat16* __restrict__ l, int n)
{
    int i = (blockIdx.x * 256 + threadIdx.x) * 4;
    if (i < n) {
        float4 v = *(const float4*)&x[i];
        float a[4] = {v.x, v.y, v.z, v.w};
        __nv_bfloat16 hh[4], ll[4];
        #pragma unroll
        for (int e = 0; e < 4; e++) split1(a[e], hh[e], ll[e]);
        __nv_bfloat162 p;
        p.x=hh[0]; p.y=hh[1]; *(__nv_bfloat162*)&h[i]   = p;
        p.x=hh[2]; p.y=hh[3]; *(__nv_bfloat162*)&h[i+2] = p;
        p.x=ll[0]; p.y=ll[1]; *(__nv_bfloat162*)&l[i]   = p;
        p.x=ll[2]; p.y=ll[3]; *(__nv_bfloat162*)&l[i+2] = p;
    }
}

// ---------------- launcher ----------------
extern "C" void kernel_launch(void* const* d_in, const int* in_sizes, int n_in,
                              void* d_out, int out_size) {
    const float* states   = (const float*)d_in[0];
    const int*   actions  = (const int*)d_in[1];
    const int*   tsteps   = (const int*)d_in[2];
    const float* W_se     = (const float*)d_in[3];
    const float* b_se     = (const float*)d_in[4];
    const float* act_tab  = (const float*)d_in[5];
    const float* pos_emb  = (const float*)d_in[6];
    const float* gpe      = (const float*)d_in[7];
    const float* ln1_g    = (const float*)d_in[8];
    const float* ln1_b    = (const float*)d_in[9];
    const float* Wq       = (const float*)d_in[10];
    const float* bq       = (const float*)d_in[11];
    const float* Wk       = (const float*)d_in[12];
    const float* bk       = (const float*)d_in[13];
    const float* Wv       = (const float*)d_in[14];
    const float* bv       = (const float*)d_in[15];
    const float* Wo       = (const float*)d_in[16];
    const float* bo       = (const float*)d_in[17];
    const float* ln2_g    = (const float*)d_in[18];
    const float* ln2_b    = (const float*)d_in[19];
    const float* W1       = (const float*)d_in[20];
    const float* b1       = (const float*)d_in[21];
    const float* W2       = (const float*)d_in[22];
    const float* b2       = (const float*)d_in[23];
    const float* lnf_g    = (const float*)d_in[24];
    const float* lnf_b    = (const float*)d_in[25];
    const float* W_head   = (const float*)d_in[26];
    float* out = (float*)d_out;

    float* F = nullptr;
    cudaGetSymbolAddress((void**)&F, g_f32);
    __nv_bfloat16* BP = nullptr;
    cudaGetSymbolAddress((void**)&BP, g_bf);

    float* X  = F;
    float* X2 = X  + N_BLC;
    float* Qb = X2 + N_BLC;
    float* Kb = Qb + N_BLC;
    float* Vb = Kb + N_BLC;
    float* HF = Vb + N_BLC;

    size_t off = 0;
    auto take = [&](size_t n) { __nv_bfloat16* p = BP + off; off += n; return p; };
    __nv_bfloat16 *stH = take(524288), *stL = take(524288);
    __nv_bfloat16 *wseH = take(131072), *wseL = take(131072);
    __nv_bfloat16 *wH[NLAYER][6], *wL[NLAYER][6];
    const size_t wsz[6] = {1048576, 1048576, 1048576, 1048576, 2097152, 2097152};
    for (int lyr = 0; lyr < NLAYER; lyr++)
        for (int j = 0; j < 6; j++) { wH[lyr][j] = take(wsz[j]); wL[lyr][j] = take(wsz[j]); }
    __nv_bfloat16 *hdH = take(4194304), *hdL = take(4194304);
    __nv_bfloat16 *HbH = take(N_BLC),   *HbL = take(N_BLC);
    __nv_bfloat16 *AOH = take(N_BLC),   *AOL = take(N_BLC);
    __nv_bfloat16 *MIDH = take(2*N_BLC), *MIDL = take(2*N_BLC);
    __nv_bfloat16 *HFH = take(N_HF),    *HFL = take(N_HF);

    const int GSM = 2*4*128*40*2;     // 81920 B
    const int ATSM = 4*64*68*4;       // 69632 B
    cudaFuncSetAttribute(gemm_kernel<1,true,false,false>, cudaFuncAttributeMaxDynamicSharedMemorySize, GSM);
    cudaFuncSetAttribute(gemm_kernel<0,true,false,false>, cudaFuncAttributeMaxDynamicSharedMemorySize, GSM);
    cudaFuncSetAttribute(gemm_kernel<0,true,true,false>,  cudaFuncAttributeMaxDynamicSharedMemorySize, GSM);
    cudaFuncSetAttribute(gemm_kernel<2,true,false,true>,  cudaFuncAttributeMaxDynamicSharedMemorySize, GSM);
    cudaFuncSetAttribute(gemm_kernel<0,false,false,false>,cudaFuncAttributeMaxDynamicSharedMemorySize, GSM);
    cudaFuncSetAttribute(attn_kernel, cudaFuncAttributeMaxDynamicSharedMemorySize, ATSM);

    const int Mx = Bb * Lseq;   // 8192
    const int Mh = Bb * Tt;     // 4096
    dim3 thr(256);

    // weight/state splits
    esplit_kernel<<<512, thr>>>(states, stH, stL, Mh * Ss);
    wsplit_kernel<<<dim3(Cc/32, Ss/32), thr>>>(W_se, wseH, wseL, Ss, Cc);
    for (int lyr = 0; lyr < NLAYER; lyr++) {
        wsplit_kernel<<<dim3(Cc/32, Cc/32), thr>>>(Wq + (size_t)lyr*Cc*Cc, wH[lyr][0], wL[lyr][0], Cc, Cc);
        wsplit_kernel<<<dim3(Cc/32, Cc/32), thr>>>(Wk + (size_t)lyr*Cc*Cc, wH[lyr][1], wL[lyr][1], Cc, Cc);
        wsplit_kernel<<<dim3(Cc/32, Cc/32), thr>>>(Wv + (size_t)lyr*Cc*Cc, wH[lyr][2], wL[lyr][2], Cc, Cc);
        wsplit_kernel<<<dim3(Cc/32, Cc/32), thr>>>(Wo + (size_t)lyr*Cc*Cc, wH[lyr][3], wL[lyr][3], Cc, Cc);
        wsplit_kernel<<<dim3(2*Cc/32, Cc/32), thr>>>(W1 + (size_t)lyr*Cc*2*Cc, wH[lyr][4], wL[lyr][4], Cc, 2*Cc);
        wsplit_kernel<<<dim3(Cc/32, 2*Cc/32), thr>>>(W2 + (size_t)lyr*2*Cc*Cc, wH[lyr][5], wL[lyr][5], 2*Cc, Cc);
    }
    wsplit_kernel<<<dim3(VOC/32, Cc/32), thr>>>(W_head, hdH, hdL, Cc, VOC);

    // state encoder + token assembly
    gemm_kernel<1,true,false,false><<<dim3(Cc/128, Mh/128), thr, GSM>>>(
        stH, stL, wseH, wseL, b_se, nullptr, HF, nullptr, nullptr, Mh, Cc, Ss);
    assemble_kernel<<<Mh, thr>>>(HF, actions, tsteps, act_tab, pos_emb, gpe, X);

    for (int lyr = 0; lyr < NLAYER; lyr++) {
        ln_kernel<<<Mx, thr>>>(X, ln1_g + lyr*Cc, ln1_b + lyr*Cc, HbH, HbL, 0);
        gemm_kernel<0,true,false,false><<<dim3(Cc/128, Mx/128), thr, GSM>>>(
            HbH, HbL, wH[lyr][0], wL[lyr][0], bq + lyr*Cc, nullptr, Qb, nullptr, nullptr, Mx, Cc, Cc);
        gemm_kernel<0,true,false,false><<<dim3(Cc/128, Mx/128), thr, GSM>>>(
            HbH, HbL, wH[lyr][1], wL[lyr][1], bk + lyr*Cc, nullptr, Kb, nullptr, nullptr, Mx, Cc, Cc);
        gemm_kernel<0,true,false,false><<<dim3(Cc/128, Mx/128), thr, GSM>>>(
            HbH, HbL, wH[lyr][2], wL[lyr][2], bv + lyr*Cc, nullptr, Vb, nullptr, nullptr, Mx, Cc, Cc);
        attn_kernel<<<dim3(Lseq/64, Bb*16), thr, ATSM>>>(Qb, Kb, Vb, AOH, AOL);
        gemm_kernel<0,true,true,false><<<dim3(Cc/128, Mx/128), thr, GSM>>>(
            AOH, AOL, wH[lyr][3], wL[lyr][3], bo + lyr*Cc, X, X2, nullptr, nullptr, Mx, Cc, Cc);
        ln_kernel<<<Mx, thr>>>(X2, ln2_g + lyr*Cc, ln2_b + lyr*Cc, HbH, HbL, 0);
        gemm_kernel<2,true,false,true><<<dim3(2*Cc/128, Mx/128), thr, GSM>>>(
            HbH, HbL, wH[lyr][4], wL[lyr][4], b1 + lyr*2*Cc, nullptr, nullptr, MIDH, MIDL, Mx, 2*Cc, Cc);
        gemm_kernel<0,true,true,false><<<dim3(Cc/128, Mx/128), thr, GSM>>>(
            MIDH, MIDL, wH[lyr][5], wL[lyr][5], b2 + lyr*Cc, X2, X, nullptr, nullptr, Mx, Cc, 2*Cc);
    }

    ln_kernel<<<Mh, thr>>>(X, lnf_g, lnf_b, HFH, HFL, 1);
    gemm_kernel<0,false,false,false><<<dim3(VOC/128, Mh/128), thr, GSM>>>(
        HFH, HFL, hdH, hdL, nullptr, nullptr, out, nullptr, nullptr, Mh, VOC, Cc);
}

// round 4
// speedup vs baseline: 3.7471x; 1.5107x over previous
#include <cuda_runtime.h>
#include <cuda_bf16.h>
#include <cstdint>

#define Bb 4
#define Tt 1024
#define Ss 128
#define Cc 1024
#define NLAYER 8
#define VOC 4096
#define Lseq 2048

#define N_BLC (Bb*Lseq*Cc)
#define N_HF  (Bb*Tt*Cc)

__device__ float g_f32[2*N_BLC + N_HF];           // X, X2, HF
__device__ __nv_bfloat16 g_bf[269746176];         // all bf16 hi/lo planes

// ---------------- helpers ----------------
__device__ __forceinline__ void ldsm4(uint32_t r[4], const __nv_bfloat16* p) {
    uint32_t a = (uint32_t)__cvta_generic_to_shared(p);
    asm volatile("ldmatrix.sync.aligned.m8n8.x4.shared.b16 {%0,%1,%2,%3}, [%4];"
        : "=r"(r[0]), "=r"(r[1]), "=r"(r[2]), "=r"(r[3]) : "r"(a));
}
__device__ __forceinline__ void ldsm4t(uint32_t r[4], const __nv_bfloat16* p) {
    uint32_t a = (uint32_t)__cvta_generic_to_shared(p);
    asm volatile("ldmatrix.sync.aligned.m8n8.x4.trans.shared.b16 {%0,%1,%2,%3}, [%4];"
        : "=r"(r[0]), "=r"(r[1]), "=r"(r[2]), "=r"(r[3]) : "r"(a));
}
__device__ __forceinline__ void mma_bf16(float c[4], const uint32_t a[4], const uint32_t b[2]) {
    asm volatile("mma.sync.aligned.m16n8k16.row.col.f32.bf16.bf16.f32 "
        "{%0,%1,%2,%3}, {%4,%5,%6,%7}, {%8,%9}, {%0,%1,%2,%3};"
        : "+f"(c[0]), "+f"(c[1]), "+f"(c[2]), "+f"(c[3])
        : "r"(a[0]), "r"(a[1]), "r"(a[2]), "r"(a[3]), "r"(b[0]), "r"(b[1]));
}
__device__ __forceinline__ void cpa16(__nv_bfloat16* dst, const __nv_bfloat16* src) {
    uint32_t d = (uint32_t)__cvta_generic_to_shared(dst);
    asm volatile("cp.async.cg.shared.global [%0], [%1], 16;" :: "r"(d), "l"(src));
}
__device__ __forceinline__ void split1(float v, __nv_bfloat16& h, __nv_bfloat16& l) {
    h = __float2bfloat16_rn(v);
    l = __float2bfloat16_rn(v - __bfloat162float(h));
}
// exp on FMA pipe (x <= 0 expected; clamped)
__device__ __forceinline__ float fast_exp(float x) {
    x = fmaxf(x, -80.f);
    float y = x * 1.44269504088896f;
    float t = y + 12582912.f;
    int ni = __float_as_int(t) - 0x4B400000;
    float f = y - (t - 12582912.f);
    float p = 1.33335581e-3f;
    p = fmaf(p, f, 9.61812910e-3f);
    p = fmaf(p, f, 5.55041087e-2f);
    p = fmaf(p, f, 2.40226507e-1f);
    p = fmaf(p, f, 6.93147180e-1f);
    p = fmaf(p, f, 1.0f);
    return p * __int_as_float((ni + 127) << 23);
}

// ---------------- GEMM (unchanged mainloop from R2) ----------------
template<int ACT, bool HASBIAS, bool HASRES, bool PLANES>
__global__ __launch_bounds__(256) void gemm_kernel(
    const __nv_bfloat16* __restrict__ Ah, const __nv_bfloat16* __restrict__ Al,
    const __nv_bfloat16* __restrict__ Wh, const __nv_bfloat16* __restrict__ Wl,
    const float* __restrict__ bias, const float* __restrict__ res,
    float* __restrict__ out, __nv_bfloat16* __restrict__ outH, __nv_bfloat16* __restrict__ outL,
    int M, int N, int K)
{
    extern __shared__ __nv_bfloat16 sm[];
    const int TILE = 128*40;
    int tid = threadIdx.x, lane = tid & 31, warp = tid >> 5;
    int bm = blockIdx.y * 128, bn = blockIdx.x * 128;
    int wm = (warp >> 1) * 32, wn = (warp & 1) * 64;

    float acc[2][8][4];
    #pragma unroll
    for (int i = 0; i < 2; i++)
        #pragma unroll
        for (int j = 0; j < 8; j++)
            #pragma unroll
            for (int q = 0; q < 4; q++) acc[i][j][q] = 0.f;

    int niter = K >> 5;

    #define ISSUE(ST, K0) do {                                                  \
        int _k0 = (K0);                                                         \
        _Pragma("unroll")                                                       \
        for (int _i = 0; _i < 8; _i++) {                                        \
            int _id = tid + (_i << 8);                                          \
            int _tile = _id >> 9;                                               \
            int _r = (_id >> 2) & 127;                                          \
            int _c = (_id & 3) << 3;                                            \
            const __nv_bfloat16* _src =                                         \
                (_tile == 0) ? Ah + (size_t)(bm + _r) * K + _k0 + _c :          \
                (_tile == 1) ? Al + (size_t)(bm + _r) * K + _k0 + _c :          \
                (_tile == 2) ? Wh + (size_t)(bn + _r) * K + _k0 + _c :          \
                               Wl + (size_t)(bn + _r) * K + _k0 + _c;           \
            cpa16(sm + ((ST)*4 + _tile)*TILE + _r*40 + _c, _src);               \
        }                                                                       \
        asm volatile("cp.async.commit_group;" ::: "memory");                    \
    } while (0)

    ISSUE(0, 0);
    for (int it = 0; it < niter; ++it) {
        if (it + 1 < niter) {
            ISSUE((it + 1) & 1, (it + 1) << 5);
            asm volatile("cp.async.wait_group 1;" ::: "memory");
        } else {
            asm volatile("cp.async.wait_group 0;" ::: "memory");
        }
        __syncthreads();
        const __nv_bfloat16* AshH = sm + (((it&1)*4 + 0) * TILE);
        const __nv_bfloat16* AshL = sm + (((it&1)*4 + 1) * TILE);
        const __nv_bfloat16* BshH = sm + (((it&1)*4 + 2) * TILE);
        const __nv_bfloat16* BshL = sm + (((it&1)*4 + 3) * TILE);

        #pragma unroll
        for (int ks = 0; ks < 2; ks++) {
            uint32_t aH[2][4], aL[2][4];
            #pragma unroll
            for (int mi = 0; mi < 2; mi++) {
                int row = wm + mi*16 + (lane & 15);
                int col = ks*16 + ((lane >> 4) << 3);
                ldsm4(aH[mi], &AshH[row*40 + col]);
                ldsm4(aL[mi], &AshL[row*40 + col]);
            }
            uint32_t bH[8][2], bL[8][2];
            #pragma unroll
            for (int pi = 0; pi < 4; pi++) {
                int nr = wn + pi*16 + ((lane >> 4) << 3) + (lane & 7);
                int kc = ks*16 + (((lane >> 3) & 1) << 3);
                uint32_t t[4];
                ldsm4(t, &BshH[nr*40 + kc]);
                bH[2*pi][0] = t[0]; bH[2*pi][1] = t[1];
                bH[2*pi+1][0] = t[2]; bH[2*pi+1][1] = t[3];
                ldsm4(t, &BshL[nr*40 + kc]);
                bL[2*pi][0] = t[0]; bL[2*pi][1] = t[1];
                bL[2*pi+1][0] = t[2]; bL[2*pi+1][1] = t[3];
            }
            #pragma unroll
            for (int mi = 0; mi < 2; mi++)
                #pragma unroll
                for (int nj = 0; nj < 8; nj++) {
                    mma_bf16(acc[mi][nj], aH[mi], bH[nj]);
                    mma_bf16(acc[mi][nj], aH[mi], bL[nj]);
                    mma_bf16(acc[mi][nj], aL[mi], bH[nj]);
                }
        }
        __syncthreads();
    }
    #undef ISSUE

    int g = lane >> 2, tg = lane & 3;
    #pragma unroll
    for (int mi = 0; mi < 2; mi++)
        #pragma unroll
        for (int nj = 0; nj < 8; nj++) {
            int r0 = bm + wm + mi*16 + g;
            int c0 = bn + wn + nj*8 + tg*2;
            float v[4];
            #pragma unroll
            for (int q = 0; q < 4; q++) {
                float x = acc[mi][nj][q];
                if (HASBIAS) x += bias[c0 + (q & 1)];
                if (ACT == 1) x = tanhf(x);
                else if (ACT == 2) x = 0.5f * x * (1.0f + erff(x * 0.70710678f));
                v[q] = x;
            }
            if (PLANES) {
                #pragma unroll
                for (int half = 0; half < 2; half++) {
                    int r = r0 + half*8;
                    __nv_bfloat16 h0, h1, l0, l1;
                    split1(v[2*half], h0, l0);
                    split1(v[2*half+1], h1, l1);
                    __nv_bfloat162 hh; hh.x = h0; hh.y = h1;
                    __nv_bfloat162 ll; ll.x = l0; ll.y = l1;
                    *(__nv_bfloat162*)&outH[(size_t)r*N + c0] = hh;
                    *(__nv_bfloat162*)&outL[(size_t)r*N + c0] = ll;
                }
            } else {
                #pragma unroll
                for (int q = 0; q < 4; q++) {
                    int r = r0 + (q >> 1) * 8, c = c0 + (q & 1);
                    float x = v[q];
                    if (HASRES) x += res[(size_t)r * N + c];
                    out[(size_t)r * N + c] = x;
                }
            }
        }
}

// ---------------- LayerNorm -> planes ----------------
__global__ __launch_bounds__(256) void ln_kernel(
    const float* __restrict__ x, const float* __restrict__ g,
    const float* __restrict__ b, __nv_bfloat16* __restrict__ oh,
    __nv_bfloat16* __restrict__ ol, int gather)
{
    int row = blockIdx.x;
    int src = gather ? ((row / Tt) * Lseq + 2 * (row % Tt) + 1) : row;
    float4 v = ((const float4*)(x + (size_t)src * Cc))[threadIdx.x];
    float s = v.x + v.y + v.z + v.w;
    float q = v.x*v.x + v.y*v.y + v.z*v.z + v.w*v.w;
    #pragma unroll
    for (int o = 16; o; o >>= 1) {
        s += __shfl_xor_sync(0xffffffffu, s, o);
        q += __shfl_xor_sync(0xffffffffu, q, o);
    }
    __shared__ float ss[8], sq[8];
    int w = threadIdx.x >> 5;
    if ((threadIdx.x & 31) == 0) { ss[w] = s; sq[w] = q; }
    __syncthreads();
    s = 0.f; q = 0.f;
    #pragma unroll
    for (int i = 0; i < 8; i++) { s += ss[i]; q += sq[i]; }
    float mean = s * (1.0f / Cc);
    float rstd = rsqrtf(q * (1.0f / Cc) - mean * mean + 1e-5f);
    float4 gv = ((const float4*)g)[threadIdx.x];
    float4 bv = ((const float4*)b)[threadIdx.x];
    float o4[4];
    o4[0] = (v.x - mean) * rstd * gv.x + bv.x;
    o4[1] = (v.y - mean) * rstd * gv.y + bv.y;
    o4[2] = (v.z - mean) * rstd * gv.z + bv.z;
    o4[3] = (v.w - mean) * rstd * gv.w + bv.w;
    size_t base = (size_t)row * Cc + threadIdx.x * 4;
    __nv_bfloat16 h[4], l[4];
    #pragma unroll
    for (int e = 0; e < 4; e++) split1(o4[e], h[e], l[e]);
    __nv_bfloat162 p;
    p.x=h[0]; p.y=h[1]; *(__nv_bfloat162*)&oh[base]   = p;
    p.x=h[2]; p.y=h[3]; *(__nv_bfloat162*)&oh[base+2] = p;
    p.x=l[0]; p.y=l[1]; *(__nv_bfloat162*)&ol[base]   = p;
    p.x=l[2]; p.y=l[3]; *(__nv_bfloat162*)&ol[base+2] = p;
}

// ---------------- token assembly ----------------
__global__ __launch_bounds__(256) void assemble_kernel(
    const float* __restrict__ SE, const int* __restrict__ actions,
    const int* __restrict__ tsteps, const float* __restrict__ act_table,
    const float* __restrict__ pos_emb, const float* __restrict__ gpe_table,
    float* __restrict__ x)
{
    int bt = blockIdx.x;
    int b = bt / Tt, t = bt % Tt;
    int a = actions[bt];
    int ts = tsteps[bt];
    size_t row0 = (size_t)(b * Lseq + 2*t) * Cc;
    for (int c = threadIdx.x; c < Cc; c += 256) {
        float gp = gpe_table[(size_t)ts * Cc + c];
        x[row0 + c]      = SE[(size_t)bt * Cc + c] + gp + pos_emb[(size_t)(2*t) * Cc + c];
        x[row0 + Cc + c] = tanhf(act_table[(size_t)a * Cc + c]) + gp + pos_emb[(size_t)(2*t+1) * Cc + c];
    }
}

// ---------------- MMA flash attention ----------------
// grid(L/64, B*H), 128 thr (4 warps, 16 q-rows each). Split-bf16 QK^T and PV.
__global__ __launch_bounds__(128) void attn_kernel(
    const __nv_bfloat16* __restrict__ QH, const __nv_bfloat16* __restrict__ QL,
    const __nv_bfloat16* __restrict__ KH, const __nv_bfloat16* __restrict__ KL,
    const __nv_bfloat16* __restrict__ VH, const __nv_bfloat16* __restrict__ VL,
    __nv_bfloat16* __restrict__ OutH, __nv_bfloat16* __restrict__ OutL)
{
    extern __shared__ __nv_bfloat16 smb[];
    __nv_bfloat16* sQH = smb;
    __nv_bfloat16* sQL = smb + 4608;
    __nv_bfloat16* sKH = smb + 2*4608;
    __nv_bfloat16* sKL = smb + 3*4608;
    __nv_bfloat16* sVH = smb + 4*4608;
    __nv_bfloat16* sVL = smb + 5*4608;

    int tid = threadIdx.x, lane = tid & 31, wid = tid >> 5;
    int b = blockIdx.y >> 4, h = blockIdx.y & 15;
    int q0 = blockIdx.x * 64;
    size_t gbase = (size_t)b * Lseq * Cc + h * 64;

    // Q planes -> smem
    #pragma unroll
    for (int i = 0; i < 8; i++) {
        int id = tid + i*128;
        int pl = id >> 9;
        int r = (id >> 3) & 63;
        int c = (id & 7) << 3;
        cpa16((pl ? sQL : sQH) + r*72 + c,
              (pl ? QL : QH) + gbase + (size_t)(q0 + r)*Cc + c);
    }
    asm volatile("cp.async.commit_group;" ::: "memory");

    float m0 = -1e30f, m1 = -1e30f, lsum0 = 0.f, lsum1 = 0.f;
    float O[8][4];
    #pragma unroll
    for (int f = 0; f < 8; f++)
        #pragma unroll
        for (int q = 0; q < 4; q++) O[f][q] = 0.f;

    int g = lane >> 2, tg = lane & 3;
    int wq = wid * 16;
    int row0 = q0 + wq + g, row1 = row0 + 8;
    int ntiles = blockIdx.x + 1;

    for (int kt = 0; kt < ntiles; kt++) {
        int j0 = kt * 64;
        #pragma unroll
        for (int i = 0; i < 16; i++) {
            int id = tid + i*128;
            int pl = id >> 9;
            int r = (id >> 3) & 63;
            int c = (id & 7) << 3;
            const __nv_bfloat16* src =
                (pl==0 ? KH : pl==1 ? KL : pl==2 ? VH : VL) + gbase + (size_t)(j0 + r)*Cc + c;
            __nv_bfloat16* dst =
                (pl==0 ? sKH : pl==1 ? sKL : pl==2 ? sVH : sVL) + r*72 + c;
            cpa16(dst, src);
        }
        asm volatile("cp.async.commit_group;" ::: "memory");
        asm volatile("cp.async.wait_group 0;" ::: "memory");
        __syncthreads();

        // S = Q K^T (3-term split)
        float S[8][4];
        #pragma unroll
        for (int f = 0; f < 8; f++)
            #pragma unroll
            for (int q = 0; q < 4; q++) S[f][q] = 0.f;

        #pragma unroll
        for (int ks = 0; ks < 4; ks++) {
            int arow = wq + (lane & 15);
            int acol = ks*16 + ((lane >> 4) << 3);
            uint32_t aH[4], aL[4];
            ldsm4(aH, sQH + arow*72 + acol);
            ldsm4(aL, sQL + arow*72 + acol);
            #pragma unroll
            for (int nb = 0; nb < 4; nb++) {
                int nr = nb*16 + ((lane >> 4) << 3) + (lane & 7);
                int kc = ks*16 + (((lane >> 3) & 1) << 3);
                uint32_t tH[4], tL[4];
                ldsm4(tH, sKH + nr*72 + kc);
                ldsm4(tL, sKL + nr*72 + kc);
                uint32_t b0H[2] = {tH[0], tH[1]}, b1H[2] = {tH[2], tH[3]};
                uint32_t b0L[2] = {tL[0], tL[1]}, b1L[2] = {tL[2], tL[3]};
                mma_bf16(S[2*nb],   aH, b0H);
                mma_bf16(S[2*nb],   aH, b0L);
                mma_bf16(S[2*nb],   aL, b0H);
                mma_bf16(S[2*nb+1], aH, b1H);
                mma_bf16(S[2*nb+1], aH, b1L);
                mma_bf16(S[2*nb+1], aL, b1H);
            }
        }

        // scale + causal mask
        #pragma unroll
        for (int f = 0; f < 8; f++) {
            int kcol = j0 + f*8 + tg*2;
            float v0 = S[f][0]*0.125f; if (kcol   > row0) v0 = -1e30f;
            float v1 = S[f][1]*0.125f; if (kcol+1 > row0) v1 = -1e30f;
            float v2 = S[f][2]*0.125f; if (kcol   > row1) v2 = -1e30f;
            float v3 = S[f][3]*0.125f; if (kcol+1 > row1) v3 = -1e30f;
            S[f][0] = v0; S[f][1] = v1; S[f][2] = v2; S[f][3] = v3;
        }
        // row max
        float r0m = -1e30f, r1m = -1e30f;
        #pragma unroll
        for (int f = 0; f < 8; f++) {
            r0m = fmaxf(r0m, fmaxf(S[f][0], S[f][1]));
            r1m = fmaxf(r1m, fmaxf(S[f][2], S[f][3]));
        }
        r0m = fmaxf(r0m, __shfl_xor_sync(0xffffffffu, r0m, 1));
        r0m = fmaxf(r0m, __shfl_xor_sync(0xffffffffu, r0m, 2));
        r1m = fmaxf(r1m, __shfl_xor_sync(0xffffffffu, r1m, 1));
        r1m = fmaxf(r1m, __shfl_xor_sync(0xffffffffu, r1m, 2));
        float mn0 = fmaxf(m0, r0m), mn1 = fmaxf(m1, r1m);
        float a0 = fast_exp(m0 - mn0), a1 = fast_exp(m1 - mn1);
        m0 = mn0; m1 = mn1;

        float s0 = 0.f, s1 = 0.f;
        #pragma unroll
        for (int f = 0; f < 8; f++) {
            float p0 = fast_exp(S[f][0] - mn0);
            float p1 = fast_exp(S[f][1] - mn0);
            float p2 = fast_exp(S[f][2] - mn1);
            float p3 = fast_exp(S[f][3] - mn1);
            S[f][0] = p0; S[f][1] = p1; S[f][2] = p2; S[f][3] = p3;
            s0 += p0 + p1; s1 += p2 + p3;
        }
        s0 += __shfl_xor_sync(0xffffffffu, s0, 1);
        s0 += __shfl_xor_sync(0xffffffffu, s0, 2);
        s1 += __shfl_xor_sync(0xffffffffu, s1, 1);
        s1 += __shfl_xor_sync(0xffffffffu, s1, 2);
        lsum0 = lsum0 * a0 + s0;
        lsum1 = lsum1 * a1 + s1;
        #pragma unroll
        for (int f = 0; f < 8; f++) {
            O[f][0] *= a0; O[f][1] *= a0;
            O[f][2] *= a1; O[f][3] *= a1;
        }

        // PV (3-term split), A = P frags from S
        #pragma unroll
        for (int ks2 = 0; ks2 < 4; ks2++) {
            uint32_t pH[4], pL[4];
            #pragma unroll
            for (int hf = 0; hf < 2; hf++) {          // acc frags 2*ks2 + hf
                int f = 2*ks2 + hf;
                __nv_bfloat16 h0,h1,h2,h3,l0,l1,l2,l3;
                split1(S[f][0], h0, l0); split1(S[f][1], h1, l1);
                split1(S[f][2], h2, l2); split1(S[f][3], h3, l3);
                __nv_bfloat162 t;
                t.x=h0; t.y=h1; pH[hf*2+0] = *(uint32_t*)&t;
                t.x=h2; t.y=h3; pH[hf*2+1] = *(uint32_t*)&t;
                t.x=l0; t.y=l1; pL[hf*2+0] = *(uint32_t*)&t;
                t.x=l2; t.y=l3; pL[hf*2+1] = *(uint32_t*)&t;
            }
            // reorder: A regs must be {f0c01, f0c23, f1c01, f1c23} -> already pH[0..3]? need
            // a[0]=row g cols 2tg (frag 2ks2), a[1]=row g+8 (frag 2ks2), a[2..3]=frag 2ks2+1
            // pH currently: [0]=f0 rows g, [1]=f0 rows g+8, [2]=f1 rows g, [3]=f1 rows g+8  == correct order
            int vrow = ks2*16 + (lane & 15);
            #pragma unroll
            for (int nb = 0; nb < 4; nb++) {
                int vcol = nb*16 + ((lane >> 4) << 3);
                uint32_t tH[4], tL[4];
                ldsm4t(tH, sVH + vrow*72 + vcol);
                ldsm4t(tL, sVL + vrow*72 + vcol);
                uint32_t b0H[2] = {tH[0], tH[1]}, b1H[2] = {tH[2], tH[3]};
                uint32_t b0L[2] = {tL[0], tL[1]}, b1L[2] = {tL[2], tL[3]};
                mma_bf16(O[2*nb],   pH, b0H);
                mma_bf16(O[2*nb],   pH, b0L);
                mma_bf16(O[2*nb],   pL, b0H);
                mma_bf16(O[2*nb+1], pH, b1H);
                mma_bf16(O[2*nb+1], pH, b1L);
                mma_bf16(O[2*nb+1], pL, b1H);
            }
        }
        __syncthreads();
    }

    float rl0 = 1.f / lsum0, rl1 = 1.f / lsum1;
    size_t t0 = (size_t)(b*Lseq + row0), t1 = (size_t)(b*Lseq + row1);
    #pragma unroll
    for (int f = 0; f < 8; f++) {
        int gcol = h*64 + f*8 + tg*2;
        __nv_bfloat16 h0,h1,l0,l1;
        split1(O[f][0]*rl0, h0, l0);
        split1(O[f][1]*rl0, h1, l1);
        __nv_bfloat162 ph, plo;
        ph.x=h0; ph.y=h1; plo.x=l0; plo.y=l1;
        *(__nv_bfloat162*)&OutH[t0*Cc + gcol] = ph;
        *(__nv_bfloat162*)&OutL[t0*Cc + gcol] = plo;
        split1(O[f][2]*rl1, h0, l0);
        split1(O[f][3]*rl1, h1, l1);
        ph.x=h0; ph.y=h1; plo.x=l0; plo.y=l1;
        *(__nv_bfloat162*)&OutH[t1*Cc + gcol] = ph;
        *(__nv_bfloat162*)&OutL[t1*Cc + gcol] = plo;
    }
}

// ---------------- weight transpose+split ----------------
__global__ __launch_bounds__(256) void wsplit_kernel(
    const float* __restrict__ W, __nv_bfloat16* __restrict__ Wh,
    __nv_bfloat16* __restrict__ Wl, int K, int N)
{
    __shared__ float tile[32][33];
    int k0 = blockIdx.y * 32, n0 = blockIdx.x * 32;
    int tx = threadIdx.x & 31, ty = threadIdx.x >> 5;
    #pragma unroll
    for (int r = ty; r < 32; r += 8)
        tile[r][tx] = W[(size_t)(k0 + r) * N + n0 + tx];
    __syncthreads();
    #pragma unroll
    for (int r = ty; r < 32; r += 8) {
        float v = tile[tx][r];
        __nv_bfloat16 h, l;
        split1(v, h, l);
        size_t dst = (size_t)(n0 + r) * K + k0 + tx;
        Wh[dst] = h; Wl[dst] = l;
    }
}

__global__ __launch_bounds__(256) void esplit_kernel(
    const float* __restrict__ x, __nv_bfloat16* __restrict__ h,
    __nv_bfloat16* __restrict__ l, int n)
{
    int i = (blockIdx.x * 256 + threadIdx.x) * 4;
    if (i < n) {
        float4 v = *(const float4*)&x[i];
        float a[4] = {v.x, v.y, v.z, v.w};
        __nv_bfloat16 hh[4], ll[4];
        #pragma unroll
        for (int e = 0; e < 4; e++) split1(a[e], hh[e], ll[e]);
        __nv_bfloat162 p;
        p.x=hh[0]; p.y=hh[1]; *(__nv_bfloat162*)&h[i]   = p;
        p.x=hh[2]; p.y=hh[3]; *(__nv_bfloat162*)&h[i+2] = p;
        p.x=ll[0]; p.y=ll[1]; *(__nv_bfloat162*)&l[i]   = p;
        p.x=ll[2]; p.y=ll[3]; *(__nv_bfloat162*)&l[i+2] = p;
    }
}

// ---------------- launcher ----------------
extern "C" void kernel_launch(void* const* d_in, const int* in_sizes, int n_in,
                              void* d_out, int out_size) {
    const float* states   = (const float*)d_in[0];
    const int*   actions  = (const int*)d_in[1];
    const int*   tsteps   = (const int*)d_in[2];
    const float* W_se     = (const float*)d_in[3];
    const float* b_se     = (const float*)d_in[4];
    const float* act_tab  = (const float*)d_in[5];
    const float* pos_emb  = (const float*)d_in[6];
    const float* gpe      = (const float*)d_in[7];
    const float* ln1_g    = (const float*)d_in[8];
    const float* ln1_b    = (const float*)d_in[9];
    const float* Wq       = (const float*)d_in[10];
    const float* bq       = (const float*)d_in[11];
    const float* Wk       = (const float*)d_in[12];
    const float* bk       = (const float*)d_in[13];
    const float* Wv       = (const float*)d_in[14];
    const float* bv       = (const float*)d_in[15];
    const float* Wo       = (const float*)d_in[16];
    const float* bo       = (const float*)d_in[17];
    const float* ln2_g    = (const float*)d_in[18];
    const float* ln2_b    = (const float*)d_in[19];
    const float* W1       = (const float*)d_in[20];
    const float* b1       = (const float*)d_in[21];
    const float* W2       = (const float*)d_in[22];
    const float* b2       = (const float*)d_in[23];
    const float* lnf_g    = (const float*)d_in[24];
    const float* lnf_b    = (const float*)d_in[25];
    const float* W_head   = (const float*)d_in[26];
    float* out = (float*)d_out;

    float* F = nullptr;
    cudaGetSymbolAddress((void**)&F, g_f32);
    __nv_bfloat16* BP = nullptr;
    cudaGetSymbolAddress((void**)&BP, g_bf);

    float* X  = F;
    float* X2 = X  + N_BLC;
    float* HF = X2 + N_BLC;

    size_t off = 0;
    auto take = [&](size_t n) { __nv_bfloat16* p = BP + off; off += n; return p; };
    __nv_bfloat16 *stH = take(524288), *stL = take(524288);
    __nv_bfloat16 *wseH = take(131072), *wseL = take(131072);
    __nv_bfloat16 *wH[NLAYER][6], *wL[NLAYER][6];
    const size_t wsz[6] = {1048576, 1048576, 1048576, 1048576, 2097152, 2097152};
    for (int lyr = 0; lyr < NLAYER; lyr++)
        for (int j = 0; j < 6; j++) { wH[lyr][j] = take(wsz[j]); wL[lyr][j] = take(wsz[j]); }
    __nv_bfloat16 *hdH = take(4194304), *hdL = take(4194304);
    __nv_bfloat16 *HbH = take(N_BLC),   *HbL = take(N_BLC);
    __nv_bfloat16 *AOH = take(N_BLC),   *AOL = take(N_BLC);
    __nv_bfloat16 *MIDH = take(2*N_BLC), *MIDL = take(2*N_BLC);
    __nv_bfloat16 *HFH = take(N_HF),    *HFL = take(N_HF);
    __nv_bfloat16 *QHp = take(N_BLC), *QLp = take(N_BLC);
    __nv_bfloat16 *KHp = take(N_BLC), *KLp = take(N_BLC);
    __nv_bfloat16 *VHp = take(N_BLC), *VLp = take(N_BLC);

    const int GSM = 2*4*128*40*2;      // 81920 B
    const int ATSM = 6*4608*2;         // 55296 B
    cudaFuncSetAttribute(gemm_kernel<1,true,false,false>, cudaFuncAttributeMaxDynamicSharedMemorySize, GSM);
    cudaFuncSetAttribute(gemm_kernel<0,true,false,true>,  cudaFuncAttributeMaxDynamicSharedMemorySize, GSM);
    cudaFuncSetAttribute(gemm_kernel<0,true,true,false>,  cudaFuncAttributeMaxDynamicSharedMemorySize, GSM);
    cudaFuncSetAttribute(gemm_kernel<2,true,false,true>,  cudaFuncAttributeMaxDynamicSharedMemorySize, GSM);
    cudaFuncSetAttribute(gemm_kernel<0,false,false,false>,cudaFuncAttributeMaxDynamicSharedMemorySize, GSM);
    cudaFuncSetAttribute(attn_kernel, cudaFuncAttributeMaxDynamicSharedMemorySize, ATSM);

    const int Mx = Bb * Lseq;   // 8192
    const int Mh = Bb * Tt;     // 4096
    dim3 thr(256);

    esplit_kernel<<<512, thr>>>(states, stH, stL, Mh * Ss);
    wsplit_kernel<<<dim3(Cc/32, Ss/32), thr>>>(W_se, wseH, wseL, Ss, Cc);
    for (int lyr = 0; lyr < NLAYER; lyr++) {
        wsplit_kernel<<<dim3(Cc/32, Cc/32), thr>>>(Wq + (size_t)lyr*Cc*Cc, wH[lyr][0], wL[lyr][0], Cc, Cc);
        wsplit_kernel<<<dim3(Cc/32, Cc/32), thr>>>(Wk + (size_t)lyr*Cc*Cc, wH[lyr][1], wL[lyr][1], Cc, Cc);
        wsplit_kernel<<<dim3(Cc/32, Cc/32), thr>>>(Wv + (size_t)lyr*Cc*Cc, wH[lyr][2], wL[lyr][2], Cc, Cc);
        wsplit_kernel<<<dim3(Cc/32, Cc/32), thr>>>(Wo + (size_t)lyr*Cc*Cc, wH[lyr][3], wL[lyr][3], Cc, Cc);
        wsplit_kernel<<<dim3(2*Cc/32, Cc/32), thr>>>(W1 + (size_t)lyr*Cc*2*Cc, wH[lyr][4], wL[lyr][4], Cc, 2*Cc);
        wsplit_kernel<<<dim3(Cc/32, 2*Cc/32), thr>>>(W2 + (size_t)lyr*2*Cc*Cc, wH[lyr][5], wL[lyr][5], 2*Cc, Cc);
    }
    wsplit_kernel<<<dim3(VOC/32, Cc/32), thr>>>(W_head, hdH, hdL, Cc, VOC);

    gemm_kernel<1,true,false,false><<<dim3(Cc/128, Mh/128), thr, GSM>>>(
        stH, stL, wseH, wseL, b_se, nullptr, HF, nullptr, nullptr, Mh, Cc, Ss);
    assemble_kernel<<<Mh, thr>>>(HF, actions, tsteps, act_tab, pos_emb, gpe, X);

    for (int lyr = 0; lyr < NLAYER; lyr++) {
        ln_kernel<<<Mx, thr>>>(X, ln1_g + lyr*Cc, ln1_b + lyr*Cc, HbH, HbL, 0);
        gemm_kernel<0,true,false,true><<<dim3(Cc/128, Mx/128), thr, GSM>>>(
            HbH, HbL, wH[lyr][0], wL[lyr][0], bq + lyr*Cc, nullptr, nullptr, QHp, QLp, Mx, Cc, Cc);
        gemm_kernel<0,true,false,true><<<dim3(Cc/128, Mx/128), thr, GSM>>>(
            HbH, HbL, wH[lyr][1], wL[lyr][1], bk + lyr*Cc, nullptr, nullptr, KHp, KLp, Mx, Cc, Cc);
        gemm_kernel<0,true,false,true><<<dim3(Cc/128, Mx/128), thr, GSM>>>(
            HbH, HbL, wH[lyr][2], wL[lyr][2], bv + lyr*Cc, nullptr, nullptr, VHp, VLp, Mx, Cc, Cc);
        attn_kernel<<<dim3(Lseq/64, Bb*16), dim3(128), ATSM>>>(
            QHp, QLp, KHp, KLp, VHp, VLp, AOH, AOL);
        gemm_kernel<0,true,true,false><<<dim3(Cc/128, Mx/128), thr, GSM>>>(
            AOH, AOL, wH[lyr][3], wL[lyr][3], bo + lyr*Cc, X, X2, nullptr, nullptr, Mx, Cc, Cc);
        ln_kernel<<<Mx, thr>>>(X2, ln2_g + lyr*Cc, ln2_b + lyr*Cc, HbH, HbL, 0);
        gemm_kernel<2,true,false,true><<<dim3(2*Cc/128, Mx/128), thr, GSM>>>(
            HbH, HbL, wH[lyr][4], wL[lyr][4], b1 + lyr*2*Cc, nullptr, nullptr, MIDH, MIDL, Mx, 2*Cc, Cc);
        gemm_kernel<0,true,true,false><<<dim3(Cc/128, Mx/128), thr, GSM>>>(
            MIDH, MIDL, wH[lyr][5], wL[lyr][5], b2 + lyr*Cc, X2, X, nullptr, nullptr, Mx, Cc, 2*Cc);
    }

    ln_kernel<<<Mh, thr>>>(X, lnf_g, lnf_b, HFH, HFL, 1);
    gemm_kernel<0,false,false,false><<<dim3(VOC/128, Mh/128), thr, GSM>>>(
        HFH, HFL, hdH, hdL, nullptr, nullptr, out, nullptr, nullptr, Mh, VOC, Cc);
}

// round 6
// speedup vs baseline: 5.3638x; 1.4315x over previous
#include <cuda_runtime.h>
#include <cuda_fp16.h>
#include <cstdint>

#define Bb 4
#define Tt 1024
#define Ss 128
#define Cc 1024
#define NLAYER 8
#define VOC 4096
#define Lseq 2048

#define N_BLC (Bb*Lseq*Cc)
#define N_HF  (Bb*Tt*Cc)

__device__ float g_f32[2*N_BLC + N_HF];       // X, X2, HF
__device__ __half g_hp[181534720];            // all fp16 planes

// ---------------- helpers ----------------
__device__ __forceinline__ void ldsm4(uint32_t r[4], const __half* p) {
    uint32_t a = (uint32_t)__cvta_generic_to_shared(p);
    asm volatile("ldmatrix.sync.aligned.m8n8.x4.shared.b16 {%0,%1,%2,%3}, [%4];"
        : "=r"(r[0]), "=r"(r[1]), "=r"(r[2]), "=r"(r[3]) : "r"(a));
}
__device__ __forceinline__ void ldsm4t(uint32_t r[4], const __half* p) {
    uint32_t a = (uint32_t)__cvta_generic_to_shared(p);
    asm volatile("ldmatrix.sync.aligned.m8n8.x4.trans.shared.b16 {%0,%1,%2,%3}, [%4];"
        : "=r"(r[0]), "=r"(r[1]), "=r"(r[2]), "=r"(r[3]) : "r"(a));
}
__device__ __forceinline__ void mma_f16(float c[4], const uint32_t a[4], const uint32_t b[2]) {
    asm volatile("mma.sync.aligned.m16n8k16.row.col.f32.f16.f16.f32 "
        "{%0,%1,%2,%3}, {%4,%5,%6,%7}, {%8,%9}, {%0,%1,%2,%3};"
        : "+f"(c[0]), "+f"(c[1]), "+f"(c[2]), "+f"(c[3])
        : "r"(a[0]), "r"(a[1]), "r"(a[2]), "r"(a[3]), "r"(b[0]), "r"(b[1]));
}
__device__ __forceinline__ void cpa16(__half* dst, const __half* src) {
    uint32_t d = (uint32_t)__cvta_generic_to_shared(dst);
    asm volatile("cp.async.cg.shared.global [%0], [%1], 16;" :: "r"(d), "l"(src));
}
__device__ __forceinline__ void split1h(float v, __half& h, __half& l) {
    h = __float2half_rn(v);
    l = __float2half_rn(v - __half2float(h));
}
__device__ __forceinline__ float fast_exp(float x) {
    x = fmaxf(x, -80.f);
    float y = x * 1.44269504088896f;
    float t = y + 12582912.f;
    int ni = __float_as_int(t) - 0x4B400000;
    float f = y - (t - 12582912.f);
    float p = 1.33335581e-3f;
    p = fmaf(p, f, 9.61812910e-3f);
    p = fmaf(p, f, 5.55041087e-2f);
    p = fmaf(p, f, 2.40226507e-1f);
    p = fmaf(p, f, 6.93147180e-1f);
    p = fmaf(p, f, 1.0f);
    return p * __int_as_float((ni + 127) << 23);
}

// ---------------- GEMM: out = act((Ah+Al)@W16^T + bias)(+res) ----------------
// A planes [M,K] fp16 hi/lo; W plane PRE-TRANSPOSED [N,K] fp16. 2 MMAs per frag.
// BM=BN=128, BK=32, 256 thr, 2-stage cp.async. PL: 0=fp32 out, 1=1 plane, 2=2 planes.
template<int ACT, bool HASBIAS, bool HASRES, int PL>
__global__ __launch_bounds__(256, 2) void gemm_hk(
    const __half* __restrict__ Ah, const __half* __restrict__ Al,
    const __half* __restrict__ Wh,
    const float* __restrict__ bias, const float* __restrict__ res,
    float* __restrict__ out, __half* __restrict__ outH, __half* __restrict__ outL,
    int M, int N, int K)
{
    extern __shared__ __half sm[];
    const int TILE = 128*40;
    int tid = threadIdx.x, lane = tid & 31, warp = tid >> 5;
    int bm = blockIdx.y * 128, bn = blockIdx.x * 128;
    int wm = (warp >> 1) * 32, wn = (warp & 1) * 64;

    float acc[2][8][4];
    #pragma unroll
    for (int i = 0; i < 2; i++)
        #pragma unroll
        for (int j = 0; j < 8; j++)
            #pragma unroll
            for (int q = 0; q < 4; q++) acc[i][j][q] = 0.f;

    int niter = K >> 5;

    // 1536 16B-chunks per stage (3 tiles x 128 rows x 4), 6 per thread
    #define ISSUE(ST, K0) do {                                                  \
        int _k0 = (K0);                                                         \
        _Pragma("unroll")                                                       \
        for (int _i = 0; _i < 6; _i++) {                                        \
            int _id = tid + (_i << 8);                                          \
            int _tile = _id >> 9;                                               \
            int _r = (_id >> 2) & 127;                                          \
            int _c = (_id & 3) << 3;                                            \
            const __half* _src =                                                \
                (_tile == 0) ? Ah + (size_t)(bm + _r) * K + _k0 + _c :          \
                (_tile == 1) ? Al + (size_t)(bm + _r) * K + _k0 + _c :          \
                               Wh + (size_t)(bn + _r) * K + _k0 + _c;           \
            cpa16(sm + ((ST)*3 + _tile)*TILE + _r*40 + _c, _src);               \
        }                                                                       \
        asm volatile("cp.async.commit_group;" ::: "memory");                    \
    } while (0)

    ISSUE(0, 0);
    for (int it = 0; it < niter; ++it) {
        if (it + 1 < niter) {
            ISSUE((it + 1) & 1, (it + 1) << 5);
            asm volatile("cp.async.wait_group 1;" ::: "memory");
        } else {
            asm volatile("cp.async.wait_group 0;" ::: "memory");
        }
        __syncthreads();
        const __half* AshH = sm + (((it&1)*3 + 0) * TILE);
        const __half* AshL = sm + (((it&1)*3 + 1) * TILE);
        const __half* BshW = sm + (((it&1)*3 + 2) * TILE);

        #pragma unroll
        for (int ks = 0; ks < 2; ks++) {
            uint32_t aH[2][4], aL[2][4];
            #pragma unroll
            for (int mi = 0; mi < 2; mi++) {
                int row = wm + mi*16 + (lane & 15);
                int col = ks*16 + ((lane >> 4) << 3);
                ldsm4(aH[mi], &AshH[row*40 + col]);
                ldsm4(aL[mi], &AshL[row*40 + col]);
            }
            uint32_t bW[8][2];
            #pragma unroll
            for (int pi = 0; pi < 4; pi++) {
                int nr = wn + pi*16 + ((lane >> 4) << 3) + (lane & 7);
                int kc = ks*16 + (((lane >> 3) & 1) << 3);
                uint32_t t[4];
                ldsm4(t, &BshW[nr*40 + kc]);
                bW[2*pi][0] = t[0]; bW[2*pi][1] = t[1];
                bW[2*pi+1][0] = t[2]; bW[2*pi+1][1] = t[3];
            }
            #pragma unroll
            for (int mi = 0; mi < 2; mi++)
                #pragma unroll
                for (int nj = 0; nj < 8; nj++) {
                    mma_f16(acc[mi][nj], aH[mi], bW[nj]);
                    mma_f16(acc[mi][nj], aL[mi], bW[nj]);
                }
        }
        __syncthreads();
    }
    #undef ISSUE

    int g = lane >> 2, tg = lane & 3;
    #pragma unroll
    for (int mi = 0; mi < 2; mi++)
        #pragma unroll
        for (int nj = 0; nj < 8; nj++) {
            int r0 = bm + wm + mi*16 + g;
            int c0 = bn + wn + nj*8 + tg*2;
            float v[4];
            #pragma unroll
            for (int q = 0; q < 4; q++) {
                float x = acc[mi][nj][q];
                if (HASBIAS) x += bias[c0 + (q & 1)];
                if (ACT == 1) x = tanhf(x);
                else if (ACT == 2) x = 0.5f * x * (1.0f + erff(x * 0.70710678f));
                v[q] = x;
            }
            if (PL == 2) {
                #pragma unroll
                for (int half2i = 0; half2i < 2; half2i++) {
                    int r = r0 + half2i*8;
                    __half h0, h1, l0, l1;
                    split1h(v[2*half2i], h0, l0);
                    split1h(v[2*half2i+1], h1, l1);
                    __half2 hh; hh.x = h0; hh.y = h1;
                    __half2 ll; ll.x = l0; ll.y = l1;
                    *(__half2*)&outH[(size_t)r*N + c0] = hh;
                    *(__half2*)&outL[(size_t)r*N + c0] = ll;
                }
            } else if (PL == 1) {
                #pragma unroll
                for (int half2i = 0; half2i < 2; half2i++) {
                    int r = r0 + half2i*8;
                    __half2 hh;
                    hh.x = __float2half_rn(v[2*half2i]);
                    hh.y = __float2half_rn(v[2*half2i+1]);
                    *(__half2*)&outH[(size_t)r*N + c0] = hh;
                }
            } else {
                #pragma unroll
                for (int q = 0; q < 4; q++) {
                    int r = r0 + (q >> 1) * 8, c = c0 + (q & 1);
                    float x = v[q];
                    if (HASRES) x += res[(size_t)r * N + c];
                    out[(size_t)r * N + c] = x;
                }
            }
        }
}

// ---------------- LayerNorm -> 2 fp16 planes ----------------
__global__ __launch_bounds__(256) void ln_kernel(
    const float* __restrict__ x, const float* __restrict__ g,
    const float* __restrict__ b, __half* __restrict__ oh,
    __half* __restrict__ ol, int gather)
{
    int row = blockIdx.x;
    int src = gather ? ((row / Tt) * Lseq + 2 * (row % Tt) + 1) : row;
    float4 v = ((const float4*)(x + (size_t)src * Cc))[threadIdx.x];
    float s = v.x + v.y + v.z + v.w;
    float q = v.x*v.x + v.y*v.y + v.z*v.z + v.w*v.w;
    #pragma unroll
    for (int o = 16; o; o >>= 1) {
        s += __shfl_xor_sync(0xffffffffu, s, o);
        q += __shfl_xor_sync(0xffffffffu, q, o);
    }
    __shared__ float ss[8], sq[8];
    int w = threadIdx.x >> 5;
    if ((threadIdx.x & 31) == 0) { ss[w] = s; sq[w] = q; }
    __syncthreads();
    s = 0.f; q = 0.f;
    #pragma unroll
    for (int i = 0; i < 8; i++) { s += ss[i]; q += sq[i]; }
    float mean = s * (1.0f / Cc);
    float rstd = rsqrtf(q * (1.0f / Cc) - mean * mean + 1e-5f);
    float4 gv = ((const float4*)g)[threadIdx.x];
    float4 bv = ((const float4*)b)[threadIdx.x];
    float o4[4];
    o4[0] = (v.x - mean) * rstd * gv.x + bv.x;
    o4[1] = (v.y - mean) * rstd * gv.y + bv.y;
    o4[2] = (v.z - mean) * rstd * gv.z + bv.z;
    o4[3] = (v.w - mean) * rstd * gv.w + bv.w;
    size_t base = (size_t)row * Cc + threadIdx.x * 4;
    __half h[4], l[4];
    #pragma unroll
    for (int e = 0; e < 4; e++) split1h(o4[e], h[e], l[e]);
    __half2 p;
    p.x=h[0]; p.y=h[1]; *(__half2*)&oh[base]   = p;
    p.x=h[2]; p.y=h[3]; *(__half2*)&oh[base+2] = p;
    p.x=l[0]; p.y=l[1]; *(__half2*)&ol[base]   = p;
    p.x=l[2]; p.y=l[3]; *(__half2*)&ol[base+2] = p;
}

// ---------------- token assembly ----------------
__global__ __launch_bounds__(256) void assemble_kernel(
    const float* __restrict__ SE, const int* __restrict__ actions,
    const int* __restrict__ tsteps, const float* __restrict__ act_table,
    const float* __restrict__ pos_emb, const float* __restrict__ gpe_table,
    float* __restrict__ x)
{
    int bt = blockIdx.x;
    int b = bt / Tt, t = bt % Tt;
    int a = actions[bt];
    int ts = tsteps[bt];
    size_t row0 = (size_t)(b * Lseq + 2*t) * Cc;
    for (int c = threadIdx.x; c < Cc; c += 256) {
        float gp = gpe_table[(size_t)ts * Cc + c];
        x[row0 + c]      = SE[(size_t)bt * Cc + c] + gp + pos_emb[(size_t)(2*t) * Cc + c];
        x[row0 + Cc + c] = tanhf(act_table[(size_t)a * Cc + c]) + gp + pos_emb[(size_t)(2*t+1) * Cc + c];
    }
}

// ---------------- MMA flash attention (fp16 2-term) ----------------
// grid(L/64, B*H), 128 thr. S=(Qh+Ql)K16^T, O=(Ph+Pl)V16.
__global__ __launch_bounds__(128) void attn_kernel(
    const __half* __restrict__ QH, const __half* __restrict__ QL,
    const __half* __restrict__ KH, const __half* __restrict__ VH,
    __half* __restrict__ OutH, __half* __restrict__ OutL)
{
    extern __shared__ __half smb[];
    __half* sQH = smb;
    __half* sQL = smb + 4608;
    __half* sKH = smb + 2*4608;
    __half* sVH = smb + 3*4608;

    int tid = threadIdx.x, lane = tid & 31, wid = tid >> 5;
    int b = blockIdx.y >> 4, h = blockIdx.y & 15;
    int q0 = blockIdx.x * 64;
    size_t gbase = (size_t)b * Lseq * Cc + h * 64;

    #pragma unroll
    for (int i = 0; i < 8; i++) {
        int id = tid + i*128;
        int pl = id >> 9;
        int r = (id >> 3) & 63;
        int c = (id & 7) << 3;
        cpa16((pl ? sQL : sQH) + r*72 + c,
              (pl ? QL : QH) + gbase + (size_t)(q0 + r)*Cc + c);
    }
    asm volatile("cp.async.commit_group;" ::: "memory");

    float m0 = -1e30f, m1 = -1e30f, lsum0 = 0.f, lsum1 = 0.f;
    float O[8][4];
    #pragma unroll
    for (int f = 0; f < 8; f++)
        #pragma unroll
        for (int q = 0; q < 4; q++) O[f][q] = 0.f;

    int g = lane >> 2, tg = lane & 3;
    int wq = wid * 16;
    int row0 = q0 + wq + g, row1 = row0 + 8;
    int ntiles = blockIdx.x + 1;

    for (int kt = 0; kt < ntiles; kt++) {
        int j0 = kt * 64;
        #pragma unroll
        for (int i = 0; i < 8; i++) {
            int id = tid + i*128;
            int pl = id >> 9;
            int r = (id >> 3) & 63;
            int c = (id & 7) << 3;
            const __half* src = (pl == 0 ? KH : VH) + gbase + (size_t)(j0 + r)*Cc + c;
            __half* dst = (pl == 0 ? sKH : sVH) + r*72 + c;
            cpa16(dst, src);
        }
        asm volatile("cp.async.commit_group;" ::: "memory");
        asm volatile("cp.async.wait_group 0;" ::: "memory");
        __syncthreads();

        float S[8][4];
        #pragma unroll
        for (int f = 0; f < 8; f++)
            #pragma unroll
            for (int q = 0; q < 4; q++) S[f][q] = 0.f;

        #pragma unroll
        for (int ks = 0; ks < 4; ks++) {
            int arow = wq + (lane & 15);
            int acol = ks*16 + ((lane >> 4) << 3);
            uint32_t aH[4], aL[4];
            ldsm4(aH, sQH + arow*72 + acol);
            ldsm4(aL, sQL + arow*72 + acol);
            #pragma unroll
            for (int nb = 0; nb < 4; nb++) {
                int nr = nb*16 + ((lane >> 4) << 3) + (lane & 7);
                int kc = ks*16 + (((lane >> 3) & 1) << 3);
                uint32_t tK[4];
                ldsm4(tK, sKH + nr*72 + kc);
                uint32_t b0[2] = {tK[0], tK[1]}, b1[2] = {tK[2], tK[3]};
                mma_f16(S[2*nb],   aH, b0);
                mma_f16(S[2*nb],   aL, b0);
                mma_f16(S[2*nb+1], aH, b1);
                mma_f16(S[2*nb+1], aL, b1);
            }
        }

        #pragma unroll
        for (int f = 0; f < 8; f++) {
            int kcol = j0 + f*8 + tg*2;
            float v0 = S[f][0]*0.125f; if (kcol   > row0) v0 = -1e30f;
            float v1 = S[f][1]*0.125f; if (kcol+1 > row0) v1 = -1e30f;
            float v2 = S[f][2]*0.125f; if (kcol   > row1) v2 = -1e30f;
            float v3 = S[f][3]*0.125f; if (kcol+1 > row1) v3 = -1e30f;
            S[f][0] = v0; S[f][1] = v1; S[f][2] = v2; S[f][3] = v3;
        }
        float r0m = -1e30f, r1m = -1e30f;
        #pragma unroll
        for (int f = 0; f < 8; f++) {
            r0m = fmaxf(r0m, fmaxf(S[f][0], S[f][1]));
            r1m = fmaxf(r1m, fmaxf(S[f][2], S[f][3]));
        }
        r0m = fmaxf(r0m, __shfl_xor_sync(0xffffffffu, r0m, 1));
        r0m = fmaxf(r0m, __shfl_xor_sync(0xffffffffu, r0m, 2));
        r1m = fmaxf(r1m, __shfl_xor_sync(0xffffffffu, r1m, 1));
        r1m = fmaxf(r1m, __shfl_xor_sync(0xffffffffu, r1m, 2));
        float mn0 = fmaxf(m0, r0m), mn1 = fmaxf(m1, r1m);
        float a0 = fast_exp(m0 - mn0), a1 = fast_exp(m1 - mn1);
        m0 = mn0; m1 = mn1;

        float s0 = 0.f, s1 = 0.f;
        #pragma unroll
        for (int f = 0; f < 8; f++) {
            float p0 = fast_exp(S[f][0] - mn0);
            float p1 = fast_exp(S[f][1] - mn0);
            float p2 = fast_exp(S[f][2] - mn1);
            float p3 = fast_exp(S[f][3] - mn1);
            S[f][0] = p0; S[f][1] = p1; S[f][2] = p2; S[f][3] = p3;
            s0 += p0 + p1; s1 += p2 + p3;
        }
        s0 += __shfl_xor_sync(0xffffffffu, s0, 1);
        s0 += __shfl_xor_sync(0xffffffffu, s0, 2);
        s1 += __shfl_xor_sync(0xffffffffu, s1, 1);
        s1 += __shfl_xor_sync(0xffffffffu, s1, 2);
        lsum0 = lsum0 * a0 + s0;
        lsum1 = lsum1 * a1 + s1;
        #pragma unroll
        for (int f = 0; f < 8; f++) {
            O[f][0] *= a0; O[f][1] *= a0;
            O[f][2] *= a1; O[f][3] *= a1;
        }

        #pragma unroll
        for (int ks2 = 0; ks2 < 4; ks2++) {
            uint32_t pH[4], pL[4];
            #pragma unroll
            for (int hf = 0; hf < 2; hf++) {
                int f = 2*ks2 + hf;
                __half h0,h1,h2,h3,l0,l1,l2,l3;
                split1h(S[f][0], h0, l0); split1h(S[f][1], h1, l1);
                split1h(S[f][2], h2, l2); split1h(S[f][3], h3, l3);
                __half2 t;
                t.x=h0; t.y=h1; pH[hf*2+0] = *(uint32_t*)&t;
                t.x=h2; t.y=h3; pH[hf*2+1] = *(uint32_t*)&t;
                t.x=l0; t.y=l1; pL[hf*2+0] = *(uint32_t*)&t;
                t.x=l2; t.y=l3; pL[hf*2+1] = *(uint32_t*)&t;
            }
            int vrow = ks2*16 + (lane & 15);
            #pragma unroll
            for (int nb = 0; nb < 4; nb++) {
                int vcol = nb*16 + ((lane >> 4) << 3);
                uint32_t tV[4];
                ldsm4t(tV, sVH + vrow*72 + vcol);
                uint32_t b0[2] = {tV[0], tV[1]}, b1[2] = {tV[2], tV[3]};
                mma_f16(O[2*nb],   pH, b0);
                mma_f16(O[2*nb],   pL, b0);
                mma_f16(O[2*nb+1], pH, b1);
                mma_f16(O[2*nb+1], pL, b1);
            }
        }
        __syncthreads();
    }

    float rl0 = 1.f / lsum0, rl1 = 1.f / lsum1;
    size_t t0 = (size_t)(b*Lseq + row0), t1 = (size_t)(b*Lseq + row1);
    #pragma unroll
    for (int f = 0; f < 8; f++) {
        int gcol = h*64 + f*8 + tg*2;
        __half h0,h1,l0,l1;
        split1h(O[f][0]*rl0, h0, l0);
        split1h(O[f][1]*rl0, h1, l1);
        __half2 ph, plo;
        ph.x=h0; ph.y=h1; plo.x=l0; plo.y=l1;
        *(__half2*)&OutH[t0*Cc + gcol] = ph;
        *(__half2*)&OutL[t0*Cc + gcol] = plo;
        split1h(O[f][2]*rl1, h0, l0);
        split1h(O[f][3]*rl1, h1, l1);
        ph.x=h0; ph.y=h1; plo.x=l0; plo.y=l1;
        *(__half2*)&OutH[t1*Cc + gcol] = ph;
        *(__half2*)&OutL[t1*Cc + gcol] = plo;
    }
}

// ---------------- weight transpose + fp16 round: W[K,N] -> Wh [N,K] ----------------
__global__ __launch_bounds__(256) void wsplit_kernel(
    const float* __restrict__ W, __half* __restrict__ Wh, int K, int N)
{
    __shared__ float tile[32][33];
    int k0 = blockIdx.y * 32, n0 = blockIdx.x * 32;
    int tx = threadIdx.x & 31, ty = threadIdx.x >> 5;
    #pragma unroll
    for (int r = ty; r < 32; r += 8)
        tile[r][tx] = W[(size_t)(k0 + r) * N + n0 + tx];
    __syncthreads();
    #pragma unroll
    for (int r = ty; r < 32; r += 8)
        Wh[(size_t)(n0 + r) * K + k0 + tx] = __float2half_rn(tile[tx][r]);
}

// ---------------- elementwise 2-plane split (states) ----------------
__global__ __launch_bounds__(256) void esplit_kernel(
    const float* __restrict__ x, __half* __restrict__ h,
    __half* __restrict__ l, int n)
{
    int i = (blockIdx.x * 256 + threadIdx.x) * 4;
    if (i < n) {
        float4 v = *(const float4*)&x[i];
        float a[4] = {v.x, v.y, v.z, v.w};
        __half hh[4], ll[4];
        #pragma unroll
        for (int e = 0; e < 4; e++) split1h(a[e], hh[e], ll[e]);
        __half2 p;
        p.x=hh[0]; p.y=hh[1]; *(__half2*)&h[i]   = p;
        p.x=hh[2]; p.y=hh[3]; *(__half2*)&h[i+2] = p;
        p.x=ll[0]; p.y=ll[1]; *(__half2*)&l[i]   = p;
        p.x=ll[2]; p.y=ll[3]; *(__half2*)&l[i+2] = p;
    }
}

// ---------------- launcher ----------------
extern "C" void kernel_launch(void* const* d_in, const int* in_sizes, int n_in,
                              void* d_out, int out_size) {
    const float* states   = (const float*)d_in[0];
    const int*   actions  = (const int*)d_in[1];
    const int*   tsteps   = (const int*)d_in[2];
    const float* W_se     = (const float*)d_in[3];
    const float* b_se     = (const float*)d_in[4];
    const float* act_tab  = (const float*)d_in[5];
    const float* pos_emb  = (const float*)d_in[6];
    const float* gpe      = (const float*)d_in[7];
    const float* ln1_g    = (const float*)d_in[8];
    const float* ln1_b    = (const float*)d_in[9];
    const float* Wq       = (const float*)d_in[10];
    const float* bq       = (const float*)d_in[11];
    const float* Wk       = (const float*)d_in[12];
    const float* bk       = (const float*)d_in[13];
    const float* Wv       = (const float*)d_in[14];
    const float* bv       = (const float*)d_in[15];
    const float* Wo       = (const float*)d_in[16];
    const float* bo       = (const float*)d_in[17];
    const float* ln2_g    = (const float*)d_in[18];
    const float* ln2_b    = (const float*)d_in[19];
    const float* W1       = (const float*)d_in[20];
    const float* b1       = (const float*)d_in[21];
    const float* W2       = (const float*)d_in[22];
    const float* b2       = (const float*)d_in[23];
    const float* lnf_g    = (const float*)d_in[24];
    const float* lnf_b    = (const float*)d_in[25];
    const float* W_head   = (const float*)d_in[26];
    float* out = (float*)d_out;

    float* F = nullptr;
    cudaGetSymbolAddress((void**)&F, g_f32);
    __half* HP = nullptr;
    cudaGetSymbolAddress((void**)&HP, g_hp);

    float* X  = F;
    float* X2 = X  + N_BLC;
    float* HF = X2 + N_BLC;

    size_t off = 0;
    auto take = [&](size_t n) { __half* p = HP + off; off += n; return p; };
    __half *stH = take(524288), *stL = take(524288);
    __half *wseH = take(131072);
    __half *wHp[NLAYER][6];
    const size_t wsz[6] = {1048576, 1048576, 1048576, 1048576, 2097152, 2097152};
    for (int lyr = 0; lyr < NLAYER; lyr++)
        for (int j = 0; j < 6; j++) wHp[lyr][j] = take(wsz[j]);
    __half *hdH = take(4194304);
    __half *HbH = take(N_BLC),   *HbL = take(N_BLC);
    __half *AOH = take(N_BLC),   *AOL = take(N_BLC);
    __half *MIDH = take(2*N_BLC), *MIDL = take(2*N_BLC);
    __half *HFH = take(N_HF),    *HFL = take(N_HF);
    __half *QHp = take(N_BLC), *QLp = take(N_BLC);
    __half *KHp = take(N_BLC);
    __half *VHp = take(N_BLC);

    const int GSM = 2*3*128*40*2;     // 61440 B
    const int ATSM = 4*4608*2;        // 36864 B
    cudaFuncSetAttribute(gemm_hk<1,true,false,0>, cudaFuncAttributeMaxDynamicSharedMemorySize, GSM);
    cudaFuncSetAttribute(gemm_hk<0,true,false,2>, cudaFuncAttributeMaxDynamicSharedMemorySize, GSM);
    cudaFuncSetAttribute(gemm_hk<0,true,false,1>, cudaFuncAttributeMaxDynamicSharedMemorySize, GSM);
    cudaFuncSetAttribute(gemm_hk<0,true,true,0>,  cudaFuncAttributeMaxDynamicSharedMemorySize, GSM);
    cudaFuncSetAttribute(gemm_hk<2,true,false,2>, cudaFuncAttributeMaxDynamicSharedMemorySize, GSM);
    cudaFuncSetAttribute(gemm_hk<0,false,false,0>,cudaFuncAttributeMaxDynamicSharedMemorySize, GSM);
    cudaFuncSetAttribute(attn_kernel, cudaFuncAttributeMaxDynamicSharedMemorySize, ATSM);

    const int Mx = Bb * Lseq;   // 8192
    const int Mh = Bb * Tt;     // 4096
    dim3 thr(256);

    esplit_kernel<<<512, thr>>>(states, stH, stL, Mh * Ss);
    wsplit_kernel<<<dim3(Cc/32, Ss/32), thr>>>(W_se, wseH, Ss, Cc);
    for (int lyr = 0; lyr < NLAYER; lyr++) {
        wsplit_kernel<<<dim3(Cc/32, Cc/32), thr>>>(Wq + (size_t)lyr*Cc*Cc, wHp[lyr][0], Cc, Cc);
        wsplit_kernel<<<dim3(Cc/32, Cc/32), thr>>>(Wk + (size_t)lyr*Cc*Cc, wHp[lyr][1], Cc, Cc);
        wsplit_kernel<<<dim3(Cc/32, Cc/32), thr>>>(Wv + (size_t)lyr*Cc*Cc, wHp[lyr][2], Cc, Cc);
        wsplit_kernel<<<dim3(Cc/32, Cc/32), thr>>>(Wo + (size_t)lyr*Cc*Cc, wHp[lyr][3], Cc, Cc);
        wsplit_kernel<<<dim3(2*Cc/32, Cc/32), thr>>>(W1 + (size_t)lyr*Cc*2*Cc, wHp[lyr][4], Cc, 2*Cc);
        wsplit_kernel<<<dim3(Cc/32, 2*Cc/32), thr>>>(W2 + (size_t)lyr*2*Cc*Cc, wHp[lyr][5], 2*Cc, Cc);
    }
    wsplit_kernel<<<dim3(VOC/32, Cc/32), thr>>>(W_head, hdH, Cc, VOC);

    gemm_hk<1,true,false,0><<<dim3(Cc/128, Mh/128), thr, GSM>>>(
        stH, stL, wseH, b_se, nullptr, HF, nullptr, nullptr, Mh, Cc, Ss);
    assemble_kernel<<<Mh, thr>>>(HF, actions, tsteps, act_tab, pos_emb, gpe, X);

    for (int lyr = 0; lyr < NLAYER; lyr++) {
        ln_kernel<<<Mx, thr>>>(X, ln1_g + lyr*Cc, ln1_b + lyr*Cc, HbH, HbL, 0);
        gemm_hk<0,true,false,2><<<dim3(Cc/128, Mx/128), thr, GSM>>>(
            HbH, HbL, wHp[lyr][0], bq + lyr*Cc, nullptr, nullptr, QHp, QLp, Mx, Cc, Cc);
        gemm_hk<0,true,false,1><<<dim3(Cc/128, Mx/128), thr, GSM>>>(
            HbH, HbL, wHp[lyr][1], bk + lyr*Cc, nullptr, nullptr, KHp, nullptr, Mx, Cc, Cc);
        gemm_hk<0,true,false,1><<<dim3(Cc/128, Mx/128), thr, GSM>>>(
            HbH, HbL, wHp[lyr][2], bv + lyr*Cc, nullptr, nullptr, VHp, nullptr, Mx, Cc, Cc);
        attn_kernel<<<dim3(Lseq/64, Bb*16), dim3(128), ATSM>>>(
            QHp, QLp, KHp, VHp, AOH, AOL);
        gemm_hk<0,true,true,0><<<dim3(Cc/128, Mx/128), thr, GSM>>>(
            AOH, AOL, wHp[lyr][3], bo + lyr*Cc, X, X2, nullptr, nullptr, Mx, Cc, Cc);
        ln_kernel<<<Mx, thr>>>(X2, ln2_g + lyr*Cc, ln2_b + lyr*Cc, HbH, HbL, 0);
        gemm_hk<2,true,false,2><<<dim3(2*Cc/128, Mx/128), thr, GSM>>>(
            HbH, HbL, wHp[lyr][4], b1 + lyr*2*Cc, nullptr, nullptr, MIDH, MIDL, Mx, 2*Cc, Cc);
        gemm_hk<0,true,true,0><<<dim3(Cc/128, Mx/128), thr, GSM>>>(
            MIDH, MIDL, wHp[lyr][5], b2 + lyr*Cc, X2, X, nullptr, nullptr, Mx, Cc, 2*Cc);
    }

    ln_kernel<<<Mh, thr>>>(X, lnf_g, lnf_b, HFH, HFL, 1);
    gemm_hk<0,false,false,0><<<dim3(VOC/128, Mh/128), thr, GSM>>>(
        HFH, HFL, hdH, nullptr, nullptr, out, nullptr, nullptr, Mh, VOC, Cc);
}

// round 7
// speedup vs baseline: 5.5533x; 1.0353x over previous
#include <cuda_runtime.h>
#include <cuda_fp16.h>
#include <cstdint>

#define Bb 4
#define Tt 1024
#define Ss 128
#define Cc 1024
#define NLAYER 8
#define VOC 4096
#define Lseq 2048

#define N_BLC (Bb*Lseq*Cc)
#define N_HF  (Bb*Tt*Cc)

__device__ float g_f32[2*N_BLC + N_HF];       // X, X2, HF
__device__ float g_bqkv[NLAYER*3072];         // fused qkv bias
__device__ __half g_hp[198311936];            // all fp16 planes (~397MB)

// ---------------- helpers ----------------
__device__ __forceinline__ void ldsm4(uint32_t r[4], const __half* p) {
    uint32_t a = (uint32_t)__cvta_generic_to_shared(p);
    asm volatile("ldmatrix.sync.aligned.m8n8.x4.shared.b16 {%0,%1,%2,%3}, [%4];"
        : "=r"(r[0]), "=r"(r[1]), "=r"(r[2]), "=r"(r[3]) : "r"(a));
}
__device__ __forceinline__ void ldsm4t(uint32_t r[4], const __half* p) {
    uint32_t a = (uint32_t)__cvta_generic_to_shared(p);
    asm volatile("ldmatrix.sync.aligned.m8n8.x4.trans.shared.b16 {%0,%1,%2,%3}, [%4];"
        : "=r"(r[0]), "=r"(r[1]), "=r"(r[2]), "=r"(r[3]) : "r"(a));
}
__device__ __forceinline__ void mma_f16(float c[4], const uint32_t a[4], const uint32_t b[2]) {
    asm volatile("mma.sync.aligned.m16n8k16.row.col.f32.f16.f16.f32 "
        "{%0,%1,%2,%3}, {%4,%5,%6,%7}, {%8,%9}, {%0,%1,%2,%3};"
        : "+f"(c[0]), "+f"(c[1]), "+f"(c[2]), "+f"(c[3])
        : "r"(a[0]), "r"(a[1]), "r"(a[2]), "r"(a[3]), "r"(b[0]), "r"(b[1]));
}
__device__ __forceinline__ void cpa16(__half* dst, const __half* src) {
    uint32_t d = (uint32_t)__cvta_generic_to_shared(dst);
    asm volatile("cp.async.cg.shared.global [%0], [%1], 16;" :: "r"(d), "l"(src));
}
__device__ __forceinline__ void split1h(float v, __half& h, __half& l) {
    h = __float2half_rn(v);
    l = __float2half_rn(v - __half2float(h));
}
__device__ __forceinline__ float fast_exp(float x) {
    x = fmaxf(x, -80.f);
    float y = x * 1.44269504088896f;
    float t = y + 12582912.f;
    int ni = __float_as_int(t) - 0x4B400000;
    float f = y - (t - 12582912.f);
    float p = 1.33335581e-3f;
    p = fmaf(p, f, 9.61812910e-3f);
    p = fmaf(p, f, 5.55041087e-2f);
    p = fmaf(p, f, 2.40226507e-1f);
    p = fmaf(p, f, 6.93147180e-1f);
    p = fmaf(p, f, 1.0f);
    return p * __int_as_float((ni + 127) << 23);
}

// ---------------- GEMM: out = act((Ah+Al)@W16^T + bias)(+res) ----------------
// 3-stage cp.async pipeline, one __syncthreads per k-iter (BK=32).
// A planes [M,K] fp16 hi/lo; W PRE-TRANSPOSED [N,K] fp16. 2 MMAs per frag.
// PL: 0=fp32 out, 1=1 plane, 2=2 planes.
template<int ACT, bool HASBIAS, bool HASRES, int PL>
__global__ __launch_bounds__(256, 2) void gemm_hk(
    const __half* __restrict__ Ah, const __half* __restrict__ Al,
    const __half* __restrict__ Wh,
    const float* __restrict__ bias, const float* __restrict__ res,
    float* __restrict__ out, __half* __restrict__ outH, __half* __restrict__ outL,
    int M, int N, int K)
{
    extern __shared__ __half sm[];
    const int TILE = 128*40;
    int tid = threadIdx.x, lane = tid & 31, warp = tid >> 5;
    int bm = blockIdx.y * 128, bn = blockIdx.x * 128;
    int wm = (warp >> 1) * 32, wn = (warp & 1) * 64;

    float acc[2][8][4];
    #pragma unroll
    for (int i = 0; i < 2; i++)
        #pragma unroll
        for (int j = 0; j < 8; j++)
            #pragma unroll
            for (int q = 0; q < 4; q++) acc[i][j][q] = 0.f;

    int niter = K >> 5;

    // 1536 16B-chunks per stage (3 tiles x 128 rows x 4), 6 per thread
    #define ISSUE(ST, K0) do {                                                  \
        int _k0 = (K0);                                                         \
        _Pragma("unroll")                                                       \
        for (int _i = 0; _i < 6; _i++) {                                        \
            int _id = tid + (_i << 8);                                          \
            int _tile = _id >> 9;                                               \
            int _r = (_id >> 2) & 127;                                          \
            int _c = (_id & 3) << 3;                                            \
            const __half* _src =                                                \
                (_tile == 0) ? Ah + (size_t)(bm + _r) * K + _k0 + _c :          \
                (_tile == 1) ? Al + (size_t)(bm + _r) * K + _k0 + _c :          \
                               Wh + (size_t)(bn + _r) * K + _k0 + _c;           \
            cpa16(sm + ((ST)*3 + _tile)*TILE + _r*40 + _c, _src);               \
        }                                                                       \
        asm volatile("cp.async.commit_group;" ::: "memory");                    \
    } while (0)

    ISSUE(0, 0);
    if (niter > 1) ISSUE(1, 32);
    for (int it = 0; it < niter; ++it) {
        if (it + 1 < niter) {
            asm volatile("cp.async.wait_group 1;" ::: "memory");
        } else {
            asm volatile("cp.async.wait_group 0;" ::: "memory");
        }
        __syncthreads();
        if (it + 2 < niter) ISSUE((it + 2) % 3, (it + 2) << 5);

        int st = it % 3;
        const __half* AshH = sm + ((st*3 + 0) * TILE);
        const __half* AshL = sm + ((st*3 + 1) * TILE);
        const __half* BshW = sm + ((st*3 + 2) * TILE);

        #pragma unroll
        for (int ks = 0; ks < 2; ks++) {
            uint32_t aH[2][4], aL[2][4];
            #pragma unroll
            for (int mi = 0; mi < 2; mi++) {
                int row = wm + mi*16 + (lane & 15);
                int col = ks*16 + ((lane >> 4) << 3);
                ldsm4(aH[mi], &AshH[row*40 + col]);
                ldsm4(aL[mi], &AshL[row*40 + col]);
            }
            uint32_t bW[8][2];
            #pragma unroll
            for (int pi = 0; pi < 4; pi++) {
                int nr = wn + pi*16 + ((lane >> 4) << 3) + (lane & 7);
                int kc = ks*16 + (((lane >> 3) & 1) << 3);
                uint32_t t[4];
                ldsm4(t, &BshW[nr*40 + kc]);
                bW[2*pi][0] = t[0]; bW[2*pi][1] = t[1];
                bW[2*pi+1][0] = t[2]; bW[2*pi+1][1] = t[3];
            }
            #pragma unroll
            for (int mi = 0; mi < 2; mi++)
                #pragma unroll
                for (int nj = 0; nj < 8; nj++) {
                    mma_f16(acc[mi][nj], aH[mi], bW[nj]);
                    mma_f16(acc[mi][nj], aL[mi], bW[nj]);
                }
        }
    }
    #undef ISSUE

    int g = lane >> 2, tg = lane & 3;
    #pragma unroll
    for (int mi = 0; mi < 2; mi++)
        #pragma unroll
        for (int nj = 0; nj < 8; nj++) {
            int r0 = bm + wm + mi*16 + g;
            int c0 = bn + wn + nj*8 + tg*2;
            float v[4];
            #pragma unroll
            for (int q = 0; q < 4; q++) {
                float x = acc[mi][nj][q];
                if (HASBIAS) x += bias[c0 + (q & 1)];
                if (ACT == 1) x = tanhf(x);
                else if (ACT == 2) x = 0.5f * x * (1.0f + erff(x * 0.70710678f));
                v[q] = x;
            }
            if (PL == 2) {
                #pragma unroll
                for (int h2 = 0; h2 < 2; h2++) {
                    int r = r0 + h2*8;
                    __half h0, h1, l0, l1;
                    split1h(v[2*h2], h0, l0);
                    split1h(v[2*h2+1], h1, l1);
                    __half2 hh; hh.x = h0; hh.y = h1;
                    __half2 ll; ll.x = l0; ll.y = l1;
                    *(__half2*)&outH[(size_t)r*N + c0] = hh;
                    *(__half2*)&outL[(size_t)r*N + c0] = ll;
                }
            } else if (PL == 1) {
                #pragma unroll
                for (int h2 = 0; h2 < 2; h2++) {
                    int r = r0 + h2*8;
                    __half2 hh;
                    hh.x = __float2half_rn(v[2*h2]);
                    hh.y = __float2half_rn(v[2*h2+1]);
                    *(__half2*)&outH[(size_t)r*N + c0] = hh;
                }
            } else {
                #pragma unroll
                for (int q = 0; q < 4; q++) {
                    int r = r0 + (q >> 1) * 8, c = c0 + (q & 1);
                    float x = v[q];
                    if (HASRES) x += res[(size_t)r * N + c];
                    out[(size_t)r * N + c] = x;
                }
            }
        }
}

// ---------------- LayerNorm -> 2 fp16 planes ----------------
__global__ __launch_bounds__(256) void ln_kernel(
    const float* __restrict__ x, const float* __restrict__ g,
    const float* __restrict__ b, __half* __restrict__ oh,
    __half* __restrict__ ol, int gather)
{
    int row = blockIdx.x;
    int src = gather ? ((row / Tt) * Lseq + 2 * (row % Tt) + 1) : row;
    float4 v = ((const float4*)(x + (size_t)src * Cc))[threadIdx.x];
    float s = v.x + v.y + v.z + v.w;
    float q = v.x*v.x + v.y*v.y + v.z*v.z + v.w*v.w;
    #pragma unroll
    for (int o = 16; o; o >>= 1) {
        s += __shfl_xor_sync(0xffffffffu, s, o);
        q += __shfl_xor_sync(0xffffffffu, q, o);
    }
    __shared__ float ss[8], sq[8];
    int w = threadIdx.x >> 5;
    if ((threadIdx.x & 31) == 0) { ss[w] = s; sq[w] = q; }
    __syncthreads();
    s = 0.f; q = 0.f;
    #pragma unroll
    for (int i = 0; i < 8; i++) { s += ss[i]; q += sq[i]; }
    float mean = s * (1.0f / Cc);
    float rstd = rsqrtf(q * (1.0f / Cc) - mean * mean + 1e-5f);
    float4 gv = ((const float4*)g)[threadIdx.x];
    float4 bv = ((const float4*)b)[threadIdx.x];
    float o4[4];
    o4[0] = (v.x - mean) * rstd * gv.x + bv.x;
    o4[1] = (v.y - mean) * rstd * gv.y + bv.y;
    o4[2] = (v.z - mean) * rstd * gv.z + bv.z;
    o4[3] = (v.w - mean) * rstd * gv.w + bv.w;
    size_t base = (size_t)row * Cc + threadIdx.x * 4;
    __half h[4], l[4];
    #pragma unroll
    for (int e = 0; e < 4; e++) split1h(o4[e], h[e], l[e]);
    __half2 p;
    p.x=h[0]; p.y=h[1]; *(__half2*)&oh[base]   = p;
    p.x=h[2]; p.y=h[3]; *(__half2*)&oh[base+2] = p;
    p.x=l[0]; p.y=l[1]; *(__half2*)&ol[base]   = p;
    p.x=l[2]; p.y=l[3]; *(__half2*)&ol[base+2] = p;
}

// ---------------- token assembly ----------------
__global__ __launch_bounds__(256) void assemble_kernel(
    const float* __restrict__ SE, const int* __restrict__ actions,
    const int* __restrict__ tsteps, const float* __restrict__ act_table,
    const float* __restrict__ pos_emb, const float* __restrict__ gpe_table,
    float* __restrict__ x)
{
    int bt = blockIdx.x;
    int b = bt / Tt, t = bt % Tt;
    int a = actions[bt];
    int ts = tsteps[bt];
    size_t row0 = (size_t)(b * Lseq + 2*t) * Cc;
    for (int c = threadIdx.x; c < Cc; c += 256) {
        float gp = gpe_table[(size_t)ts * Cc + c];
        x[row0 + c]      = SE[(size_t)bt * Cc + c] + gp + pos_emb[(size_t)(2*t) * Cc + c];
        x[row0 + Cc + c] = tanhf(act_table[(size_t)a * Cc + c]) + gp + pos_emb[(size_t)(2*t+1) * Cc + c];
    }
}

// ---------------- MMA flash attention (fp16 2-term), fused QKV input ----------------
// QKV planes: [B*L, 3072], Q at col 0, K at 1024, V at 2048.
__global__ __launch_bounds__(128) void attn_kernel(
    const __half* __restrict__ QKVH, const __half* __restrict__ QKVL,
    __half* __restrict__ OutH, __half* __restrict__ OutL)
{
    extern __shared__ __half smb[];
    __half* sQH = smb;
    __half* sQL = smb + 4608;
    __half* sKH = smb + 2*4608;
    __half* sVH = smb + 3*4608;

    int tid = threadIdx.x, lane = tid & 31, wid = tid >> 5;
    int b = blockIdx.y >> 4, h = blockIdx.y & 15;
    int q0 = blockIdx.x * 64;
    size_t gbase = (size_t)b * Lseq * 3072 + h * 64;

    #pragma unroll
    for (int i = 0; i < 8; i++) {
        int id = tid + i*128;
        int pl = id >> 9;
        int r = (id >> 3) & 63;
        int c = (id & 7) << 3;
        cpa16((pl ? sQL : sQH) + r*72 + c,
              (pl ? QKVL : QKVH) + gbase + (size_t)(q0 + r)*3072 + c);
    }
    asm volatile("cp.async.commit_group;" ::: "memory");

    float m0 = -1e30f, m1 = -1e30f, lsum0 = 0.f, lsum1 = 0.f;
    float O[8][4];
    #pragma unroll
    for (int f = 0; f < 8; f++)
        #pragma unroll
        for (int q = 0; q < 4; q++) O[f][q] = 0.f;

    int g = lane >> 2, tg = lane & 3;
    int wq = wid * 16;
    int row0 = q0 + wq + g, row1 = row0 + 8;
    int ntiles = blockIdx.x + 1;

    for (int kt = 0; kt < ntiles; kt++) {
        int j0 = kt * 64;
        #pragma unroll
        for (int i = 0; i < 8; i++) {
            int id = tid + i*128;
            int pl = id >> 9;                 // 0: K, 1: V
            int r = (id >> 3) & 63;
            int c = (id & 7) << 3;
            const __half* src = QKVH + gbase + (size_t)(j0 + r)*3072 + (pl ? 2048 : 1024) + c;
            __half* dst = (pl ? sVH : sKH) + r*72 + c;
            cpa16(dst, src);
        }
        asm volatile("cp.async.commit_group;" ::: "memory");
        asm volatile("cp.async.wait_group 0;" ::: "memory");
        __syncthreads();

        float S[8][4];
        #pragma unroll
        for (int f = 0; f < 8; f++)
            #pragma unroll
            for (int q = 0; q < 4; q++) S[f][q] = 0.f;

        #pragma unroll
        for (int ks = 0; ks < 4; ks++) {
            int arow = wq + (lane & 15);
            int acol = ks*16 + ((lane >> 4) << 3);
            uint32_t aH[4], aL[4];
            ldsm4(aH, sQH + arow*72 + acol);
            ldsm4(aL, sQL + arow*72 + acol);
            #pragma unroll
            for (int nb = 0; nb < 4; nb++) {
                int nr = nb*16 + ((lane >> 4) << 3) + (lane & 7);
                int kc = ks*16 + (((lane >> 3) & 1) << 3);
                uint32_t tK[4];
                ldsm4(tK, sKH + nr*72 + kc);
                uint32_t b0[2] = {tK[0], tK[1]}, b1[2] = {tK[2], tK[3]};
                mma_f16(S[2*nb],   aH, b0);
                mma_f16(S[2*nb],   aL, b0);
                mma_f16(S[2*nb+1], aH, b1);
                mma_f16(S[2*nb+1], aL, b1);
            }
        }

        #pragma unroll
        for (int f = 0; f < 8; f++) {
            int kcol = j0 + f*8 + tg*2;
            float v0 = S[f][0]*0.125f; if (kcol   > row0) v0 = -1e30f;
            float v1 = S[f][1]*0.125f; if (kcol+1 > row0) v1 = -1e30f;
            float v2 = S[f][2]*0.125f; if (kcol   > row1) v2 = -1e30f;
            float v3 = S[f][3]*0.125f; if (kcol+1 > row1) v3 = -1e30f;
            S[f][0] = v0; S[f][1] = v1; S[f][2] = v2; S[f][3] = v3;
        }
        float r0m = -1e30f, r1m = -1e30f;
        #pragma unroll
        for (int f = 0; f < 8; f++) {
            r0m = fmaxf(r0m, fmaxf(S[f][0], S[f][1]));
            r1m = fmaxf(r1m, fmaxf(S[f][2], S[f][3]));
        }
        r0m = fmaxf(r0m, __shfl_xor_sync(0xffffffffu, r0m, 1));
        r0m = fmaxf(r0m, __shfl_xor_sync(0xffffffffu, r0m, 2));
        r1m = fmaxf(r1m, __shfl_xor_sync(0xffffffffu, r1m, 1));
        r1m = fmaxf(r1m, __shfl_xor_sync(0xffffffffu, r1m, 2));
        float mn0 = fmaxf(m0, r0m), mn1 = fmaxf(m1, r1m);
        float a0 = fast_exp(m0 - mn0), a1 = fast_exp(m1 - mn1);
        m0 = mn0; m1 = mn1;

        float s0 = 0.f, s1 = 0.f;
        #pragma unroll
        for (int f = 0; f < 8; f++) {
            float p0 = fast_exp(S[f][0] - mn0);
            float p1 = fast_exp(S[f][1] - mn0);
            float p2 = fast_exp(S[f][2] - mn1);
            float p3 = fast_exp(S[f][3] - mn1);
            S[f][0] = p0; S[f][1] = p1; S[f][2] = p2; S[f][3] = p3;
            s0 += p0 + p1; s1 += p2 + p3;
        }
        s0 += __shfl_xor_sync(0xffffffffu, s0, 1);
        s0 += __shfl_xor_sync(0xffffffffu, s0, 2);
        s1 += __shfl_xor_sync(0xffffffffu, s1, 1);
        s1 += __shfl_xor_sync(0xffffffffu, s1, 2);
        lsum0 = lsum0 * a0 + s0;
        lsum1 = lsum1 * a1 + s1;
        #pragma unroll
        for (int f = 0; f < 8; f++) {
            O[f][0] *= a0; O[f][1] *= a0;
            O[f][2] *= a1; O[f][3] *= a1;
        }

        #pragma unroll
        for (int ks2 = 0; ks2 < 4; ks2++) {
            uint32_t pH[4], pL[4];
            #pragma unroll
            for (int hf = 0; hf < 2; hf++) {
                int f = 2*ks2 + hf;
                __half h0,h1,h2,h3,l0,l1,l2,l3;
                split1h(S[f][0], h0, l0); split1h(S[f][1], h1, l1);
                split1h(S[f][2], h2, l2); split1h(S[f][3], h3, l3);
                __half2 t;
                t.x=h0; t.y=h1; pH[hf*2+0] = *(uint32_t*)&t;
                t.x=h2; t.y=h3; pH[hf*2+1] = *(uint32_t*)&t;
                t.x=l0; t.y=l1; pL[hf*2+0] = *(uint32_t*)&t;
                t.x=l2; t.y=l3; pL[hf*2+1] = *(uint32_t*)&t;
            }
            int vrow = ks2*16 + (lane & 15);
            #pragma unroll
            for (int nb = 0; nb < 4; nb++) {
                int vcol = nb*16 + ((lane >> 4) << 3);
                uint32_t tV[4];
                ldsm4t(tV, sVH + vrow*72 + vcol);
                uint32_t b0[2] = {tV[0], tV[1]}, b1[2] = {tV[2], tV[3]};
                mma_f16(O[2*nb],   pH, b0);
                mma_f16(O[2*nb],   pL, b0);
                mma_f16(O[2*nb+1], pH, b1);
                mma_f16(O[2*nb+1], pL, b1);
            }
        }
        __syncthreads();
    }

    float rl0 = 1.f / lsum0, rl1 = 1.f / lsum1;
    size_t t0 = (size_t)(b*Lseq + row0), t1 = (size_t)(b*Lseq + row1);
    #pragma unroll
    for (int f = 0; f < 8; f++) {
        int gcol = h*64 + f*8 + tg*2;
        __half h0,h1,l0,l1;
        split1h(O[f][0]*rl0, h0, l0);
        split1h(O[f][1]*rl0, h1, l1);
        __half2 ph, plo;
        ph.x=h0; ph.y=h1; plo.x=l0; plo.y=l1;
        *(__half2*)&OutH[t0*Cc + gcol] = ph;
        *(__half2*)&OutL[t0*Cc + gcol] = plo;
        split1h(O[f][2]*rl1, h0, l0);
        split1h(O[f][3]*rl1, h1, l1);
        ph.x=h0; ph.y=h1; plo.x=l0; plo.y=l1;
        *(__half2*)&OutH[t1*Cc + gcol] = ph;
        *(__half2*)&OutL[t1*Cc + gcol] = plo;
    }
}

// ---------------- batched weight transpose + fp16: W[K,N] -> Wh [N,K], z=layer ----------------
__global__ __launch_bounds__(256) void wsplit_kernel(
    const float* __restrict__ W, __half* __restrict__ Wh, int K, int N,
    size_t inStride, size_t outStride)
{
    const float* Wz = W + (size_t)blockIdx.z * inStride;
    __half* Whz = Wh + (size_t)blockIdx.z * outStride;
    __shared__ float tile[32][33];
    int k0 = blockIdx.y * 32, n0 = blockIdx.x * 32;
    int tx = threadIdx.x & 31, ty = threadIdx.x >> 5;
    #pragma unroll
    for (int r = ty; r < 32; r += 8)
        tile[r][tx] = Wz[(size_t)(k0 + r) * N + n0 + tx];
    __syncthreads();
    #pragma unroll
    for (int r = ty; r < 32; r += 8)
        Whz[(size_t)(n0 + r) * K + k0 + tx] = __float2half_rn(tile[tx][r]);
}

// ---------------- fused QKV bias concat ----------------
__global__ __launch_bounds__(256) void bcat_kernel(
    const float* __restrict__ bq, const float* __restrict__ bk,
    const float* __restrict__ bv, float* __restrict__ outb)
{
    int i = blockIdx.x * 256 + threadIdx.x;
    if (i < NLAYER * 3072) {
        int lyr = i / 3072, c = i % 3072;
        float v = (c < 1024) ? bq[lyr*1024 + c]
                : (c < 2048) ? bk[lyr*1024 + c - 1024]
                             : bv[lyr*1024 + c - 2048];
        outb[i] = v;
    }
}

// ---------------- elementwise 2-plane split (states) ----------------
__global__ __launch_bounds__(256) void esplit_kernel(
    const float* __restrict__ x, __half* __restrict__ h,
    __half* __restrict__ l, int n)
{
    int i = (blockIdx.x * 256 + threadIdx.x) * 4;
    if (i < n) {
        float4 v = *(const float4*)&x[i];
        float a[4] = {v.x, v.y, v.z, v.w};
        __half hh[4], ll[4];
        #pragma unroll
        for (int e = 0; e < 4; e++) split1h(a[e], hh[e], ll[e]);
        __half2 p;
        p.x=hh[0]; p.y=hh[1]; *(__half2*)&h[i]   = p;
        p.x=hh[2]; p.y=hh[3]; *(__half2*)&h[i+2] = p;
        p.x=ll[0]; p.y=ll[1]; *(__half2*)&l[i]   = p;
        p.x=ll[2]; p.y=ll[3]; *(__half2*)&l[i+2] = p;
    }
}

// ---------------- launcher ----------------
extern "C" void kernel_launch(void* const* d_in, const int* in_sizes, int n_in,
                              void* d_out, int out_size) {
    const float* states   = (const float*)d_in[0];
    const int*   actions  = (const int*)d_in[1];
    const int*   tsteps   = (const int*)d_in[2];
    const float* W_se     = (const float*)d_in[3];
    const float* b_se     = (const float*)d_in[4];
    const float* act_tab  = (const float*)d_in[5];
    const float* pos_emb  = (const float*)d_in[6];
    const float* gpe      = (const float*)d_in[7];
    const float* ln1_g    = (const float*)d_in[8];
    const float* ln1_b    = (const float*)d_in[9];
    const float* Wq       = (const float*)d_in[10];
    const float* bq       = (const float*)d_in[11];
    const float* Wk       = (const float*)d_in[12];
    const float* bk       = (const float*)d_in[13];
    const float* Wv       = (const float*)d_in[14];
    const float* bv       = (const float*)d_in[15];
    const float* Wo       = (const float*)d_in[16];
    const float* bo       = (const float*)d_in[17];
    const float* ln2_g    = (const float*)d_in[18];
    const float* ln2_b    = (const float*)d_in[19];
    const float* W1       = (const float*)d_in[20];
    const float* b1       = (const float*)d_in[21];
    const float* W2       = (const float*)d_in[22];
    const float* b2       = (const float*)d_in[23];
    const float* lnf_g    = (const float*)d_in[24];
    const float* lnf_b    = (const float*)d_in[25];
    const float* W_head   = (const float*)d_in[26];
    float* out = (float*)d_out;

    float* F = nullptr;
    cudaGetSymbolAddress((void**)&F, g_f32);
    float* BQKV = nullptr;
    cudaGetSymbolAddress((void**)&BQKV, g_bqkv);
    __half* HP = nullptr;
    cudaGetSymbolAddress((void**)&HP, g_hp);

    float* X  = F;
    float* X2 = X  + N_BLC;
    float* HF = X2 + N_BLC;

    size_t off = 0;
    auto take = [&](size_t n) { __half* p = HP + off; off += n; return p; };
    __half *stH = take(524288), *stL = take(524288);
    __half *wseH = take(131072);
    __half *wAll = take(67108864);     // per layer: [qkv 3.1M][wo 1.0M][w1 2.1M][w2 2.1M]
    __half *hdH = take(4194304);
    __half *HbH = take(N_BLC),   *HbL = take(N_BLC);
    __half *AOH = take(N_BLC),   *AOL = take(N_BLC);
    __half *MIDH = take(2*N_BLC), *MIDL = take(2*N_BLC);
    __half *HFH = take(N_HF),    *HFL = take(N_HF);
    __half *QKVH = take(3*N_BLC), *QKVL = take(3*N_BLC);

    const size_t LW = 8388608;          // per-layer weight stride (halves)
    const size_t OFF_QKV = 0, OFF_WO = 3145728, OFF_W1 = 4194304, OFF_W2 = 6291456;

    const int GSM = 3*3*128*40*2;       // 92160 B (3 stages)
    const int ATSM = 4*4608*2;          // 36864 B
    cudaFuncSetAttribute(gemm_hk<1,true,false,0>, cudaFuncAttributeMaxDynamicSharedMemorySize, GSM);
    cudaFuncSetAttribute(gemm_hk<0,true,false,2>, cudaFuncAttributeMaxDynamicSharedMemorySize, GSM);
    cudaFuncSetAttribute(gemm_hk<0,true,true,0>,  cudaFuncAttributeMaxDynamicSharedMemorySize, GSM);
    cudaFuncSetAttribute(gemm_hk<2,true,false,2>, cudaFuncAttributeMaxDynamicSharedMemorySize, GSM);
    cudaFuncSetAttribute(gemm_hk<0,false,false,0>,cudaFuncAttributeMaxDynamicSharedMemorySize, GSM);
    cudaFuncSetAttribute(attn_kernel, cudaFuncAttributeMaxDynamicSharedMemorySize, ATSM);

    const int Mx = Bb * Lseq;   // 8192
    const int Mh = Bb * Tt;     // 4096
    dim3 thr(256);

    // ---- prep (batched) ----
    esplit_kernel<<<512, thr>>>(states, stH, stL, Mh * Ss);
    bcat_kernel<<<96, thr>>>(bq, bk, bv, BQKV);
    wsplit_kernel<<<dim3(Cc/32, Ss/32, 1), thr>>>(W_se, wseH, Ss, Cc, 0, 0);
    wsplit_kernel<<<dim3(Cc/32, Cc/32, NLAYER), thr>>>(Wq, wAll + OFF_QKV,            Cc, Cc,   (size_t)Cc*Cc,   LW);
    wsplit_kernel<<<dim3(Cc/32, Cc/32, NLAYER), thr>>>(Wk, wAll + OFF_QKV + 1024*Cc,  Cc, Cc,   (size_t)Cc*Cc,   LW);
    wsplit_kernel<<<dim3(Cc/32, Cc/32, NLAYER), thr>>>(Wv, wAll + OFF_QKV + 2048*Cc,  Cc, Cc,   (size_t)Cc*Cc,   LW);
    wsplit_kernel<<<dim3(Cc/32, Cc/32, NLAYER), thr>>>(Wo, wAll + OFF_WO,             Cc, Cc,   (size_t)Cc*Cc,   LW);
    wsplit_kernel<<<dim3(2*Cc/32, Cc/32, NLAYER), thr>>>(W1, wAll + OFF_W1,           Cc, 2*Cc, (size_t)2*Cc*Cc, LW);
    wsplit_kernel<<<dim3(Cc/32, 2*Cc/32, NLAYER), thr>>>(W2, wAll + OFF_W2,           2*Cc, Cc, (size_t)2*Cc*Cc, LW);
    wsplit_kernel<<<dim3(VOC/32, Cc/32, 1), thr>>>(W_head, hdH, Cc, VOC, 0, 0);

    // ---- state encoder + token assembly ----
    gemm_hk<1,true,false,0><<<dim3(Cc/128, Mh/128), thr, GSM>>>(
        stH, stL, wseH, b_se, nullptr, HF, nullptr, nullptr, Mh, Cc, Ss);
    assemble_kernel<<<Mh, thr>>>(HF, actions, tsteps, act_tab, pos_emb, gpe, X);

    for (int lyr = 0; lyr < NLAYER; lyr++) {
        __half* wqkv = wAll + lyr*LW + OFF_QKV;
        __half* wo   = wAll + lyr*LW + OFF_WO;
        __half* w1   = wAll + lyr*LW + OFF_W1;
        __half* w2   = wAll + lyr*LW + OFF_W2;

        ln_kernel<<<Mx, thr>>>(X, ln1_g + lyr*Cc, ln1_b + lyr*Cc, HbH, HbL, 0);
        gemm_hk<0,true,false,2><<<dim3(3072/128, Mx/128), thr, GSM>>>(
            HbH, HbL, wqkv, BQKV + lyr*3072, nullptr, nullptr, QKVH, QKVL, Mx, 3072, Cc);
        attn_kernel<<<dim3(Lseq/64, Bb*16), dim3(128), ATSM>>>(QKVH, QKVL, AOH, AOL);
        gemm_hk<0,true,true,0><<<dim3(Cc/128, Mx/128), thr, GSM>>>(
            AOH, AOL, wo, bo + lyr*Cc, X, X2, nullptr, nullptr, Mx, Cc, Cc);
        ln_kernel<<<Mx, thr>>>(X2, ln2_g + lyr*Cc, ln2_b + lyr*Cc, HbH, HbL, 0);
        gemm_hk<2,true,false,2><<<dim3(2*Cc/128, Mx/128), thr, GSM>>>(
            HbH, HbL, w1, b1 + lyr*2*Cc, nullptr, nullptr, MIDH, MIDL, Mx, 2*Cc, Cc);
        gemm_hk<0,true,true,0><<<dim3(Cc/128, Mx/128), thr, GSM>>>(
            MIDH, MIDL, w2, b2 + lyr*Cc, X2, X, nullptr, nullptr, Mx, Cc, 2*Cc);
    }

    ln_kernel<<<Mh, thr>>>(X, lnf_g, lnf_b, HFH, HFL, 1);
    gemm_hk<0,false,false,0><<<dim3(VOC/128, Mh/128), thr, GSM>>>(
        HFH, HFL, hdH, nullptr, nullptr, out, nullptr, nullptr, Mh, VOC, Cc);
}